// round 1
// baseline (speedup 1.0000x reference)
#include <cuda_runtime.h>

#define cB 128
#define cN 128
#define cM 16
#define cK 8
#define cH 16
#define cD 64
#define cE 262144
#define NSUM 16384

// ---------------- device scratch (no allocations allowed) ----------------
__device__ __align__(16) float g_feat[cB * cK * cN * cM];   // [b][k][n*16+m]   8 MB
__device__ __align__(16) float g_h1[NSUM * cM * cH];        // [node][m][h]    16.7 MB
__device__ __align__(16) float g_h2[NSUM * cM * cD];        // [node][m][d]    67 MB
__device__ int g_cnt[NSUM];
__device__ int g_rowptr[NSUM + 1];
__device__ int g_cursor[NSUM];
__device__ int g_colsrc[cE];

// ---------------- K1: polynomial filter: feat[b][k] = (lap^k @ W0)[b] ----------------
__global__ void __launch_bounds__(512) k_poly(const float* __restrict__ lap,
                                              const float* __restrict__ W0) {
    extern __shared__ float sm[];
    float* lapS = sm;                  // [128][129] padded (conflict-free row reads)
    float* buf0 = lapS + 128 * 129;    // [128][20] padded
    float* buf1 = buf0 + 128 * 20;
    const int b = blockIdx.x;
    const int t = threadIdx.x;

    const float* lapG = lap + (size_t)b * cN * cN;
    for (int i = t; i < cN * cN; i += 512)
        lapS[(i >> 7) * 129 + (i & 127)] = lapG[i];

    const float* w0G = W0 + (size_t)b * cN * cM;
    float* featG = g_feat + (size_t)b * (cK * cN * cM);
    for (int i = t; i < cN * cM; i += 512) {
        float v = w0G[i];
        buf0[(i >> 4) * 20 + (i & 15)] = v;
        featG[i] = v;                  // k = 0 plane
    }
    __syncthreads();

    const int n = t >> 2, mg = t & 3;
    float* Wc = buf0;
    float* Wn = buf1;
    const float* lrow = lapS + n * 129;
    for (int k = 1; k < cK; k++) {
        float a0 = 0.f, a1 = 0.f, a2 = 0.f, a3 = 0.f;
        #pragma unroll 8
        for (int j = 0; j < cN; j++) {
            const float l = lrow[j];
            const float4 w = *(const float4*)(Wc + j * 20 + mg * 4);
            a0 = fmaf(l, w.x, a0);
            a1 = fmaf(l, w.y, a1);
            a2 = fmaf(l, w.z, a2);
            a3 = fmaf(l, w.w, a3);
        }
        *(float4*)(Wn + n * 20 + mg * 4) = make_float4(a0, a1, a2, a3);
        ((float4*)(featG + k * (cN * cM)))[t] = make_float4(a0, a1, a2, a3);
        __syncthreads();
        float* tmp = Wc; Wc = Wn; Wn = tmp;
    }
}

// ---------------- K1b: per-graph MLP(K->H) + BatchNorm(train) + relu -> g_h1 ----------------
__global__ void __launch_bounds__(256) k_mlpbn(const float* __restrict__ mlpW,
                                               const float* __restrict__ mlpb,
                                               const float* __restrict__ bng,
                                               const float* __restrict__ bnb) {
    __shared__ float wS[cK * cH];
    __shared__ float bS[cH];
    __shared__ float red[8][32];
    __shared__ float scaleS[cH], shiftS[cH];
    const int b = blockIdx.x, t = threadIdx.x;
    if (t < cK * cH) wS[t] = mlpW[t];
    if (t < cH) bS[t] = mlpb[t];
    __syncthreads();

    const float* fG = g_feat + (size_t)b * (cK * cN * cM);
    float sum[cH], sq[cH];
    #pragma unroll
    for (int c = 0; c < cH; c++) { sum[c] = 0.f; sq[c] = 0.f; }

    for (int r = t; r < cN * cM; r += 256) {
        float f[cK];
        #pragma unroll
        for (int k = 0; k < cK; k++) f[k] = fG[k * (cN * cM) + r];
        #pragma unroll
        for (int c = 0; c < cH; c++) {
            float h = bS[c];
            #pragma unroll
            for (int k = 0; k < cK; k++) h = fmaf(f[k], wS[k * cH + c], h);
            sum[c] += h; sq[c] += h * h;
        }
    }
    #pragma unroll
    for (int c = 0; c < cH; c++)
        for (int o = 16; o; o >>= 1) {
            sum[c] += __shfl_xor_sync(0xffffffffu, sum[c], o);
            sq[c]  += __shfl_xor_sync(0xffffffffu, sq[c],  o);
        }
    const int wid = t >> 5, lane = t & 31;
    if (lane == 0) {
        #pragma unroll
        for (int c = 0; c < cH; c++) { red[wid][c] = sum[c]; red[wid][16 + c] = sq[c]; }
    }
    __syncthreads();
    if (t < 32) {
        float v = 0.f;
        for (int w2 = 0; w2 < 8; w2++) v += red[w2][t];
        red[0][t] = v;
    }
    __syncthreads();
    if (t < cH) {
        const float mu = red[0][t] * (1.f / 2048.f);
        const float var = red[0][16 + t] * (1.f / 2048.f) - mu * mu;
        const float sc = bng[t] * rsqrtf(var + 1e-5f);
        scaleS[t] = sc;
        shiftS[t] = bnb[t] - mu * sc;
    }
    __syncthreads();

    float* h1G = g_h1 + (size_t)b * (cN * cM * cH);
    for (int r = t; r < cN * cM; r += 256) {
        float f[cK];
        #pragma unroll
        for (int k = 0; k < cK; k++) f[k] = fG[k * (cN * cM) + r];
        float o[cH];
        #pragma unroll
        for (int c = 0; c < cH; c++) {
            float h = bS[c];
            #pragma unroll
            for (int k = 0; k < cK; k++) h = fmaf(f[k], wS[k * cH + c], h);
            o[c] = fmaxf(fmaf(h, scaleS[c], shiftS[c]), 0.f);
        }
        float4* dst = (float4*)(h1G + r * cH);
        dst[0] = make_float4(o[0], o[1], o[2], o[3]);
        dst[1] = make_float4(o[4], o[5], o[6], o[7]);
        dst[2] = make_float4(o[8], o[9], o[10], o[11]);
        dst[3] = make_float4(o[12], o[13], o[14], o[15]);
    }
}

// ---------------- CSR build (counting sort by dst) ----------------
__global__ void k_zero() {
    int i = blockIdx.x * blockDim.x + threadIdx.x;
    if (i < NSUM) g_cnt[i] = 0;
}
__global__ void k_hist(const int* __restrict__ ei) {
    const int stride = gridDim.x * blockDim.x;
    for (int e = blockIdx.x * blockDim.x + threadIdx.x; e < cE; e += stride)
        atomicAdd(&g_cnt[ei[cE + e]], 1);
}
__global__ void __launch_bounds__(512) k_scan() {
    __shared__ int wsum[16], woff[16];
    const int t = threadIdx.x, lane = t & 31, wid = t >> 5;
    const int base = t * 32;
    int s = 0;
    for (int i = 0; i < 32; i++) s += g_cnt[base + i];
    int v = s;
    for (int o = 1; o < 32; o <<= 1) {
        int u = __shfl_up_sync(0xffffffffu, v, o);
        if (lane >= o) v += u;
    }
    if (lane == 31) wsum[wid] = v;
    __syncthreads();
    if (t == 0) {
        int r = 0;
        for (int w2 = 0; w2 < 16; w2++) { woff[w2] = r; r += wsum[w2]; }
    }
    __syncthreads();
    int run = woff[wid] + (v - s);
    for (int i = 0; i < 32; i++) {
        const int c = g_cnt[base + i];
        g_rowptr[base + i] = run;
        g_cursor[base + i] = run;
        run += c;
    }
    if (t == 511) g_rowptr[NSUM] = run;
}
__global__ void k_scatter(const int* __restrict__ ei) {
    const int stride = gridDim.x * blockDim.x;
    for (int e = blockIdx.x * blockDim.x + threadIdx.x; e < cE; e += stride) {
        const int d = ei[cE + e];
        const int p = atomicAdd(&g_cursor[d], 1);
        g_colsrc[p] = ei[e];
    }
}

// ---------------- shared register-tiled GEMM helper (128 rows x 64 cols tile) ----------------
template <int KDIM, int ASTRIDE>
__device__ __forceinline__ void gemm_tile(const float* __restrict__ A,
                                          const float* __restrict__ W,
                                          int rc, int cc, float acc[4][8]) {
    #pragma unroll 4
    for (int k = 0; k < KDIM; k++) {
        float av[4];
        #pragma unroll
        for (int i = 0; i < 4; i++) av[i] = A[(4 * rc + i) * ASTRIDE + k];
        const float4 wlo = *(const float4*)(W + k * 64 + cc * 8);
        const float4 whi = *(const float4*)(W + k * 64 + cc * 8 + 4);
        const float wv[8] = {wlo.x, wlo.y, wlo.z, wlo.w, whi.x, whi.y, whi.z, whi.w};
        #pragma unroll
        for (int i = 0; i < 4; i++)
            #pragma unroll
            for (int q = 0; q < 8; q++)
                acc[i][q] = fmaf(av[i], wv[q], acc[i][q]);
    }
}

// ---------------- K3: fused GIN layer 1 (agg on 16-dim + MLP 16->64->64) -> g_h2 ----------------
__global__ void __launch_bounds__(256) k_gin1(const float* __restrict__ eps1p,
                                              const float* __restrict__ W1a,
                                              const float* __restrict__ b1a,
                                              const float* __restrict__ W1b,
                                              const float* __restrict__ b1b) {
    extern __shared__ float sm[];
    float* zt = sm;                  // [128][17]
    float* at = zt + 128 * 17;       // [128][65]
    float* wa = at + 128 * 65;       // 16*64
    float* wb = wa + 1024;           // 64*64
    float* ba = wb + 4096;
    float* bb = ba + 64;
    const int t = threadIdx.x, blk = blockIdx.x;

    for (int i = t; i < 1024; i += 256) wa[i] = W1a[i];
    for (int i = t; i < 4096; i += 256) wb[i] = W1b[i];
    if (t < 64) { ba[t] = b1a[t]; bb[t] = b1b[t]; }

    const float eps1 = 1.f + eps1p[0];
    const int w = t >> 5, lane = t & 31;
    const int node = blk * 8 + w;
    {
        float4 a0 = make_float4(0.f, 0.f, 0.f, 0.f);
        float4 a1 = make_float4(0.f, 0.f, 0.f, 0.f);
        const int s0 = g_rowptr[node], s1 = g_rowptr[node + 1];
        for (int e = s0; e < s1; e++) {
            const float4* hp = (const float4*)(g_h1 + g_colsrc[e] * (cM * cH));
            const float4 v0 = hp[lane];
            const float4 v1 = hp[32 + lane];
            a0.x += v0.x; a0.y += v0.y; a0.z += v0.z; a0.w += v0.w;
            a1.x += v1.x; a1.y += v1.y; a1.z += v1.z; a1.w += v1.w;
        }
        const float4* hp = (const float4*)(g_h1 + node * (cM * cH));
        const float4 v0 = hp[lane];
        const float4 v1 = hp[32 + lane];
        a0.x = fmaf(eps1, v0.x, a0.x); a0.y = fmaf(eps1, v0.y, a0.y);
        a0.z = fmaf(eps1, v0.z, a0.z); a0.w = fmaf(eps1, v0.w, a0.w);
        a1.x = fmaf(eps1, v1.x, a1.x); a1.y = fmaf(eps1, v1.y, a1.y);
        a1.z = fmaf(eps1, v1.z, a1.z); a1.w = fmaf(eps1, v1.w, a1.w);
        // element e = 4*lane (+q) and 128 + 4*lane (+q); m = e/16, c = e%16
        const int m0 = lane >> 2, c0 = (lane & 3) * 4;
        float* z0 = zt + (w * 16 + m0) * 17 + c0;
        z0[0] = a0.x; z0[1] = a0.y; z0[2] = a0.z; z0[3] = a0.w;
        float* z1 = zt + (w * 16 + 8 + m0) * 17 + c0;
        z1[0] = a1.x; z1[1] = a1.y; z1[2] = a1.z; z1[3] = a1.w;
    }
    __syncthreads();

    const int rc = t >> 3, cc = t & 7;
    float acc[4][8];
    #pragma unroll
    for (int i = 0; i < 4; i++)
        #pragma unroll
        for (int q = 0; q < 8; q++) acc[i][q] = 0.f;
    gemm_tile<16, 17>(zt, wa, rc, cc, acc);
    #pragma unroll
    for (int i = 0; i < 4; i++)
        #pragma unroll
        for (int q = 0; q < 8; q++)
            at[(4 * rc + i) * 65 + cc * 8 + q] = fmaxf(acc[i][q] + ba[cc * 8 + q], 0.f);
    __syncthreads();

    float acc2[4][8];
    #pragma unroll
    for (int i = 0; i < 4; i++)
        #pragma unroll
        for (int q = 0; q < 8; q++) acc2[i][q] = 0.f;
    gemm_tile<64, 65>(at, wb, rc, cc, acc2);

    float* outG = g_h2 + (size_t)(blk * 128) * cD;
    #pragma unroll
    for (int i = 0; i < 4; i++) {
        float y[8];
        #pragma unroll
        for (int q = 0; q < 8; q++) y[q] = fmaxf(acc2[i][q] + bb[cc * 8 + q], 0.f);
        float4* dst = (float4*)(outG + (4 * rc + i) * 64 + cc * 8);
        dst[0] = make_float4(y[0], y[1], y[2], y[3]);
        dst[1] = make_float4(y[4], y[5], y[6], y[7]);
    }
}

// ---------------- K4: fused GIN layer 2 (agg on 64-dim + MLP 64->64->64 + m-sum) -> out ----------------
__global__ void __launch_bounds__(256) k_gin2(const float* __restrict__ eps2p,
                                              const float* __restrict__ W2a,
                                              const float* __restrict__ b2a,
                                              const float* __restrict__ W2b,
                                              const float* __restrict__ b2b,
                                              float* __restrict__ out) {
    extern __shared__ float sm[];
    float* zt = sm;                   // [128][65]
    float* at = zt + 128 * 65;        // [128][65]
    float* wa = at + 128 * 65;        // 64*64
    float* wb = wa + 4096;            // 64*64
    float* ba = wb + 4096;
    float* bb = ba + 64;
    const int t = threadIdx.x, blk = blockIdx.x;

    for (int i = t; i < 4096; i += 256) { wa[i] = W2a[i]; wb[i] = W2b[i]; }
    if (t < 64) { ba[t] = b2a[t]; bb[t] = b2b[t]; }

    const float eps2 = 1.f + eps2p[0];
    const int w = t >> 5, lane = t & 31;
    const int node = blk * 8 + w;
    {
        float4 acc[8];
        #pragma unroll
        for (int j = 0; j < 8; j++) acc[j] = make_float4(0.f, 0.f, 0.f, 0.f);
        const int s0 = g_rowptr[node], s1 = g_rowptr[node + 1];
        for (int e = s0; e < s1; e++) {
            const float4* hp = (const float4*)(g_h2 + (size_t)g_colsrc[e] * (cM * cD));
            #pragma unroll
            for (int j = 0; j < 8; j++) {
                const float4 v = hp[j * 32 + lane];
                acc[j].x += v.x; acc[j].y += v.y; acc[j].z += v.z; acc[j].w += v.w;
            }
        }
        const float4* hp = (const float4*)(g_h2 + (size_t)node * (cM * cD));
        #pragma unroll
        for (int j = 0; j < 8; j++) {
            const float4 v = hp[j * 32 + lane];
            acc[j].x = fmaf(eps2, v.x, acc[j].x);
            acc[j].y = fmaf(eps2, v.y, acc[j].y);
            acc[j].z = fmaf(eps2, v.z, acc[j].z);
            acc[j].w = fmaf(eps2, v.w, acc[j].w);
        }
        #pragma unroll
        for (int j = 0; j < 8; j++) {
            const int e0 = j * 128 + lane * 4;     // element index within node row (1024)
            const int m = e0 >> 6, c = e0 & 63;
            float* zp = zt + (w * 16 + m) * 65 + c;
            zp[0] = acc[j].x; zp[1] = acc[j].y; zp[2] = acc[j].z; zp[3] = acc[j].w;
        }
    }
    __syncthreads();

    const int rc = t >> 3, cc = t & 7;
    float acc[4][8];
    #pragma unroll
    for (int i = 0; i < 4; i++)
        #pragma unroll
        for (int q = 0; q < 8; q++) acc[i][q] = 0.f;
    gemm_tile<64, 65>(zt, wa, rc, cc, acc);
    #pragma unroll
    for (int i = 0; i < 4; i++)
        #pragma unroll
        for (int q = 0; q < 8; q++)
            at[(4 * rc + i) * 65 + cc * 8 + q] = fmaxf(acc[i][q] + ba[cc * 8 + q], 0.f);
    __syncthreads();

    float acc2[4][8];
    #pragma unroll
    for (int i = 0; i < 4; i++)
        #pragma unroll
        for (int q = 0; q < 8; q++) acc2[i][q] = 0.f;
    gemm_tile<64, 65>(at, wb, rc, cc, acc2);

    // relu + partial sum over this thread's 4 m-rows (all within one node)
    float part[8];
    #pragma unroll
    for (int q = 0; q < 8; q++) {
        float s = 0.f;
        #pragma unroll
        for (int i = 0; i < 4; i++) s += fmaxf(acc2[i][q] + bb[cc * 8 + q], 0.f);
        part[q] = s;
    }
    // reduce across the 4 row-subgroups (lane bits 3,4)
    #pragma unroll
    for (int q = 0; q < 8; q++) {
        part[q] += __shfl_xor_sync(0xffffffffu, part[q], 8);
        part[q] += __shfl_xor_sync(0xffffffffu, part[q], 16);
    }
    if (lane < 8) {   // cc == lane
        float4* dst = (float4*)(out + (size_t)node * 64 + cc * 8);
        dst[0] = make_float4(part[0], part[1], part[2], part[3]);
        dst[1] = make_float4(part[4], part[5], part[6], part[7]);
    }
}

// ---------------- launch ----------------
extern "C" void kernel_launch(void* const* d_in, const int* in_sizes, int n_in,
                              void* d_out, int out_size) {
    (void)in_sizes; (void)n_in; (void)out_size;
    const float* lap  = (const float*)d_in[0];
    const float* W0   = (const float*)d_in[1];
    const float* mlpW = (const float*)d_in[2];
    const float* mlpb = (const float*)d_in[3];
    const float* bng  = (const float*)d_in[4];
    const float* bnb  = (const float*)d_in[5];
    const float* eps1 = (const float*)d_in[6];
    const float* W1a  = (const float*)d_in[7];
    const float* b1a  = (const float*)d_in[8];
    const float* W1b  = (const float*)d_in[9];
    const float* b1b  = (const float*)d_in[10];
    const float* eps2 = (const float*)d_in[11];
    const float* W2a  = (const float*)d_in[12];
    const float* b2a  = (const float*)d_in[13];
    const float* W2b  = (const float*)d_in[14];
    const float* b2b  = (const float*)d_in[15];
    const int*   ei   = (const int*)d_in[16];
    float* out = (float*)d_out;

    const int sm1 = (128 * 129 + 2 * 128 * 20) * (int)sizeof(float);            // ~86.5 KB
    const int sm3 = (128 * 17 + 128 * 65 + 1024 + 4096 + 128) * (int)sizeof(float); // ~63 KB
    const int sm4 = (2 * 128 * 65 + 2 * 4096 + 128) * (int)sizeof(float);       // ~100 KB
    cudaFuncSetAttribute(k_poly, cudaFuncAttributeMaxDynamicSharedMemorySize, sm1);
    cudaFuncSetAttribute(k_gin1, cudaFuncAttributeMaxDynamicSharedMemorySize, sm3);
    cudaFuncSetAttribute(k_gin2, cudaFuncAttributeMaxDynamicSharedMemorySize, sm4);

    k_poly<<<cB, 512, sm1>>>(lap, W0);
    k_zero<<<(NSUM + 255) / 256, 256>>>();
    k_hist<<<256, 256>>>(ei);
    k_mlpbn<<<cB, 256>>>(mlpW, mlpb, bng, bnb);
    k_scan<<<1, 512>>>();
    k_scatter<<<256, 256>>>(ei);
    k_gin1<<<NSUM / 8, 256, sm3>>>(eps1, W1a, b1a, W1b, b1b);
    k_gin2<<<NSUM / 8, 256, sm4>>>(eps2, W2a, b2a, W2b, b2b, out);
}

// round 6
// speedup vs baseline: 1.0266x; 1.0266x over previous
#include <cuda_runtime.h>
#include <cuda_fp16.h>

#define cB 128
#define cN 128
#define cM 16
#define cK 8
#define cH 16
#define cD 64
#define cE 262144
#define NSUM 16384

// ---------------- device scratch (no allocations allowed) ----------------
__device__ __align__(16) float  g_feat[cB * cK * cN * cM];   // [b][k][n*16+m]   8 MB
__device__ __align__(16) __half g_h1[NSUM * cM * cH];        // [node][m][h]     8.4 MB (fp16)
__device__ __align__(16) __half g_h2[NSUM * cM * cD];        // [node][m][d]     33.5 MB (fp16)
__device__ int g_cnt[NSUM];
__device__ int g_rowptr[NSUM + 1];
__device__ int g_cursor[NSUM];
__device__ int g_colsrc[cE];

// accumulate 8 packed halves into fp32 accumulators
__device__ __forceinline__ void acc8(float* a, uint4 v) {
    const __half2* p = (const __half2*)&v;
    #pragma unroll
    for (int j = 0; j < 4; j++) {
        const float2 f = __half22float2(p[j]);
        a[2 * j] += f.x; a[2 * j + 1] += f.y;
    }
}
__device__ __forceinline__ void fma8(float* a, uint4 v, float s) {
    const __half2* p = (const __half2*)&v;
    #pragma unroll
    for (int j = 0; j < 4; j++) {
        const float2 f = __half22float2(p[j]);
        a[2 * j] = fmaf(s, f.x, a[2 * j]);
        a[2 * j + 1] = fmaf(s, f.y, a[2 * j + 1]);
    }
}

// ---------------- K1: polynomial filter: feat[b][k] = (lap^k @ W0)[b] ----------------
__global__ void __launch_bounds__(512) k_poly(const float* __restrict__ lap,
                                              const float* __restrict__ W0) {
    extern __shared__ float sm[];
    float* lapS = sm;                  // [128][129] padded
    float* buf0 = lapS + 128 * 129;    // [128][20] padded
    float* buf1 = buf0 + 128 * 20;
    const int b = blockIdx.x;
    const int t = threadIdx.x;

    const float* lapG = lap + (size_t)b * cN * cN;
    for (int i = t; i < cN * cN; i += 512)
        lapS[(i >> 7) * 129 + (i & 127)] = lapG[i];

    const float* w0G = W0 + (size_t)b * cN * cM;
    float* featG = g_feat + (size_t)b * (cK * cN * cM);
    for (int i = t; i < cN * cM; i += 512) {
        float v = w0G[i];
        buf0[(i >> 4) * 20 + (i & 15)] = v;
        featG[i] = v;                  // k = 0 plane
    }
    __syncthreads();

    const int n = t >> 2, mg = t & 3;
    float* Wc = buf0;
    float* Wn = buf1;
    const float* lrow = lapS + n * 129;
    for (int k = 1; k < cK; k++) {
        float a0 = 0.f, a1 = 0.f, a2 = 0.f, a3 = 0.f;
        #pragma unroll 8
        for (int j = 0; j < cN; j++) {
            const float l = lrow[j];
            const float4 w = *(const float4*)(Wc + j * 20 + mg * 4);
            a0 = fmaf(l, w.x, a0);
            a1 = fmaf(l, w.y, a1);
            a2 = fmaf(l, w.z, a2);
            a3 = fmaf(l, w.w, a3);
        }
        *(float4*)(Wn + n * 20 + mg * 4) = make_float4(a0, a1, a2, a3);
        ((float4*)(featG + k * (cN * cM)))[t] = make_float4(a0, a1, a2, a3);
        __syncthreads();
        float* tmp = Wc; Wc = Wn; Wn = tmp;
    }
}

// ---------------- K1b: per-graph MLP(K->H) + BatchNorm(train) + relu -> g_h1 (fp16) ----------------
__global__ void __launch_bounds__(256) k_mlpbn(const float* __restrict__ mlpW,
                                               const float* __restrict__ mlpb,
                                               const float* __restrict__ bng,
                                               const float* __restrict__ bnb) {
    __shared__ float wS[cK * cH];
    __shared__ float bS[cH];
    __shared__ float red[8][32];
    __shared__ float scaleS[cH], shiftS[cH];
    const int b = blockIdx.x, t = threadIdx.x;
    if (t < cK * cH) wS[t] = mlpW[t];
    if (t < cH) bS[t] = mlpb[t];
    __syncthreads();

    const float* fG = g_feat + (size_t)b * (cK * cN * cM);
    float sum[cH], sq[cH];
    #pragma unroll
    for (int c = 0; c < cH; c++) { sum[c] = 0.f; sq[c] = 0.f; }

    for (int r = t; r < cN * cM; r += 256) {
        float f[cK];
        #pragma unroll
        for (int k = 0; k < cK; k++) f[k] = fG[k * (cN * cM) + r];
        #pragma unroll
        for (int c = 0; c < cH; c++) {
            float h = bS[c];
            #pragma unroll
            for (int k = 0; k < cK; k++) h = fmaf(f[k], wS[k * cH + c], h);
            sum[c] += h; sq[c] += h * h;
        }
    }
    #pragma unroll
    for (int c = 0; c < cH; c++)
        for (int o = 16; o; o >>= 1) {
            sum[c] += __shfl_xor_sync(0xffffffffu, sum[c], o);
            sq[c]  += __shfl_xor_sync(0xffffffffu, sq[c],  o);
        }
    const int wid = t >> 5, lane = t & 31;
    if (lane == 0) {
        #pragma unroll
        for (int c = 0; c < cH; c++) { red[wid][c] = sum[c]; red[wid][16 + c] = sq[c]; }
    }
    __syncthreads();
    if (t < 32) {
        float v = 0.f;
        for (int w2 = 0; w2 < 8; w2++) v += red[w2][t];
        red[0][t] = v;
    }
    __syncthreads();
    if (t < cH) {
        const float mu = red[0][t] * (1.f / 2048.f);
        const float var = red[0][16 + t] * (1.f / 2048.f) - mu * mu;
        const float sc = bng[t] * rsqrtf(var + 1e-5f);
        scaleS[t] = sc;
        shiftS[t] = bnb[t] - mu * sc;
    }
    __syncthreads();

    __half* h1G = g_h1 + (size_t)b * (cN * cM * cH);
    for (int r = t; r < cN * cM; r += 256) {
        float f[cK];
        #pragma unroll
        for (int k = 0; k < cK; k++) f[k] = fG[k * (cN * cM) + r];
        float o[cH];
        #pragma unroll
        for (int c = 0; c < cH; c++) {
            float h = bS[c];
            #pragma unroll
            for (int k = 0; k < cK; k++) h = fmaf(f[k], wS[k * cH + c], h);
            o[c] = fmaxf(fmaf(h, scaleS[c], shiftS[c]), 0.f);
        }
        uint4 pk[2];
        #pragma unroll
        for (int g = 0; g < 2; g++) {
            __half2* pp = (__half2*)&pk[g];
            #pragma unroll
            for (int j = 0; j < 4; j++)
                pp[j] = __floats2half2_rn(o[g * 8 + 2 * j], o[g * 8 + 2 * j + 1]);
        }
        uint4* dst = (uint4*)(h1G + r * cH);
        dst[0] = pk[0]; dst[1] = pk[1];
    }
}

// ---------------- CSR build (counting sort by dst) ----------------
__global__ void k_zero() {
    int i = blockIdx.x * blockDim.x + threadIdx.x;
    if (i < NSUM) g_cnt[i] = 0;
}
__global__ void k_hist(const int* __restrict__ ei) {
    const int stride = gridDim.x * blockDim.x;
    for (int e = blockIdx.x * blockDim.x + threadIdx.x; e < cE; e += stride)
        atomicAdd(&g_cnt[ei[cE + e]], 1);
}
__global__ void __launch_bounds__(512) k_scan() {
    __shared__ int wsum[16], woff[16];
    const int t = threadIdx.x, lane = t & 31, wid = t >> 5;
    const int base = t * 32;
    int s = 0;
    for (int i = 0; i < 32; i++) s += g_cnt[base + i];
    int v = s;
    for (int o = 1; o < 32; o <<= 1) {
        int u = __shfl_up_sync(0xffffffffu, v, o);
        if (lane >= o) v += u;
    }
    if (lane == 31) wsum[wid] = v;
    __syncthreads();
    if (t == 0) {
        int r = 0;
        for (int w2 = 0; w2 < 16; w2++) { woff[w2] = r; r += wsum[w2]; }
    }
    __syncthreads();
    int run = woff[wid] + (v - s);
    for (int i = 0; i < 32; i++) {
        const int c = g_cnt[base + i];
        g_rowptr[base + i] = run;
        g_cursor[base + i] = run;
        run += c;
    }
    if (t == 511) g_rowptr[NSUM] = run;
}
__global__ void k_scatter(const int* __restrict__ ei) {
    const int stride = gridDim.x * blockDim.x;
    for (int e = blockIdx.x * blockDim.x + threadIdx.x; e < cE; e += stride) {
        const int d = ei[cE + e];
        const int p = atomicAdd(&g_cursor[d], 1);
        g_colsrc[p] = ei[e];
    }
}

// ---------------- shared register-tiled GEMM helper (128 rows x 64 cols tile) ----------------
template <int KDIM, int ASTRIDE>
__device__ __forceinline__ void gemm_tile(const float* __restrict__ A,
                                          const float* __restrict__ W,
                                          int rc, int cc, float acc[4][8]) {
    #pragma unroll 4
    for (int k = 0; k < KDIM; k++) {
        float av[4];
        #pragma unroll
        for (int i = 0; i < 4; i++) av[i] = A[(4 * rc + i) * ASTRIDE + k];
        const float4 wlo = *(const float4*)(W + k * 64 + cc * 8);
        const float4 whi = *(const float4*)(W + k * 64 + cc * 8 + 4);
        const float wv[8] = {wlo.x, wlo.y, wlo.z, wlo.w, whi.x, whi.y, whi.z, whi.w};
        #pragma unroll
        for (int i = 0; i < 4; i++)
            #pragma unroll
            for (int q = 0; q < 8; q++)
                acc[i][q] = fmaf(av[i], wv[q], acc[i][q]);
    }
}

// ---------------- K3: fused GIN layer 1 (agg on fp16 16-dim + MLP 16->64->64) -> g_h2 fp16 ----------------
__global__ void __launch_bounds__(256) k_gin1(const float* __restrict__ eps1p,
                                              const float* __restrict__ W1a,
                                              const float* __restrict__ b1a,
                                              const float* __restrict__ W1b,
                                              const float* __restrict__ b1b) {
    extern __shared__ float sm[];
    float* zt = sm;                  // [128][17]
    float* at = zt + 128 * 17;       // [128][65]
    float* wa = at + 128 * 65;       // 16*64
    float* wb = wa + 1024;           // 64*64
    float* ba = wb + 4096;
    float* bb = ba + 64;
    const int t = threadIdx.x, blk = blockIdx.x;

    for (int i = t; i < 1024; i += 256) wa[i] = W1a[i];
    for (int i = t; i < 4096; i += 256) wb[i] = W1b[i];
    if (t < 64) { ba[t] = b1a[t]; bb[t] = b1b[t]; }

    const float eps1 = 1.f + eps1p[0];
    const int w = t >> 5, lane = t & 31;
    const int node = blk * 8 + w;
    {
        float a[8];
        #pragma unroll
        for (int j = 0; j < 8; j++) a[j] = 0.f;
        const int s0 = g_rowptr[node], s1 = g_rowptr[node + 1];
        int e = s0;
        for (; e + 4 <= s1; e += 4) {
            const int c0 = g_colsrc[e], c1 = g_colsrc[e + 1];
            const int c2 = g_colsrc[e + 2], c3 = g_colsrc[e + 3];
            const uint4 v0 = ((const uint4*)(g_h1 + c0 * (cM * cH)))[lane];
            const uint4 v1 = ((const uint4*)(g_h1 + c1 * (cM * cH)))[lane];
            const uint4 v2 = ((const uint4*)(g_h1 + c2 * (cM * cH)))[lane];
            const uint4 v3 = ((const uint4*)(g_h1 + c3 * (cM * cH)))[lane];
            acc8(a, v0); acc8(a, v1); acc8(a, v2); acc8(a, v3);
        }
        for (; e < s1; e++) {
            const uint4 v = ((const uint4*)(g_h1 + g_colsrc[e] * (cM * cH)))[lane];
            acc8(a, v);
        }
        const uint4 vs = ((const uint4*)(g_h1 + node * (cM * cH)))[lane];
        fma8(a, vs, eps1);
        // lane covers elements 8*lane..8*lane+7 of node row: m = lane>>1, c0 = (lane&1)*8
        float* zp = zt + (w * 16 + (lane >> 1)) * 17 + (lane & 1) * 8;
        #pragma unroll
        for (int j = 0; j < 8; j++) zp[j] = a[j];
    }
    __syncthreads();

    const int rc = t >> 3, cc = t & 7;
    float acc[4][8];
    #pragma unroll
    for (int i = 0; i < 4; i++)
        #pragma unroll
        for (int q = 0; q < 8; q++) acc[i][q] = 0.f;
    gemm_tile<16, 17>(zt, wa, rc, cc, acc);
    #pragma unroll
    for (int i = 0; i < 4; i++)
        #pragma unroll
        for (int q = 0; q < 8; q++)
            at[(4 * rc + i) * 65 + cc * 8 + q] = fmaxf(acc[i][q] + ba[cc * 8 + q], 0.f);
    __syncthreads();

    float acc2[4][8];
    #pragma unroll
    for (int i = 0; i < 4; i++)
        #pragma unroll
        for (int q = 0; q < 8; q++) acc2[i][q] = 0.f;
    gemm_tile<64, 65>(at, wb, rc, cc, acc2);

    __half* outG = g_h2 + (size_t)(blk * 128) * cD;
    #pragma unroll
    for (int i = 0; i < 4; i++) {
        uint4 pk;
        __half2* pp = (__half2*)&pk;
        #pragma unroll
        for (int j = 0; j < 4; j++) {
            const float y0 = fmaxf(acc2[i][2 * j] + bb[cc * 8 + 2 * j], 0.f);
            const float y1 = fmaxf(acc2[i][2 * j + 1] + bb[cc * 8 + 2 * j + 1], 0.f);
            pp[j] = __floats2half2_rn(y0, y1);
        }
        *(uint4*)(outG + (4 * rc + i) * 64 + cc * 8) = pk;
    }
}

// ---------------- K4: fused GIN layer 2 (agg on fp16 64-dim + MLP 64->64->64 + m-sum) -> out ----------------
__global__ void __launch_bounds__(256) k_gin2(const float* __restrict__ eps2p,
                                              const float* __restrict__ W2a,
                                              const float* __restrict__ b2a,
                                              const float* __restrict__ W2b,
                                              const float* __restrict__ b2b,
                                              float* __restrict__ out) {
    extern __shared__ float sm[];
    float* zt = sm;                   // [128][65]
    float* at = zt + 128 * 65;        // [128][65]
    float* wa = at + 128 * 65;        // 64*64
    float* wb = wa + 4096;            // 64*64
    float* ba = wb + 4096;
    float* bb = ba + 64;
    const int t = threadIdx.x, blk = blockIdx.x;

    for (int i = t; i < 4096; i += 256) { wa[i] = W2a[i]; wb[i] = W2b[i]; }
    if (t < 64) { ba[t] = b2a[t]; bb[t] = b2b[t]; }

    const float eps2 = 1.f + eps2p[0];
    const int w = t >> 5, lane = t & 31;
    const int node = blk * 8 + w;
    {
        float a[32];
        #pragma unroll
        for (int j = 0; j < 32; j++) a[j] = 0.f;
        const int s0 = g_rowptr[node], s1 = g_rowptr[node + 1];
        int e = s0;
        for (; e + 2 <= s1; e += 2) {
            const uint4* p0 = (const uint4*)(g_h2 + (size_t)g_colsrc[e] * (cM * cD));
            const uint4* p1 = (const uint4*)(g_h2 + (size_t)g_colsrc[e + 1] * (cM * cD));
            uint4 v[8];
            #pragma unroll
            for (int j = 0; j < 4; j++) v[j] = p0[4 * lane + j];
            #pragma unroll
            for (int j = 0; j < 4; j++) v[4 + j] = p1[4 * lane + j];
            #pragma unroll
            for (int j = 0; j < 4; j++) { acc8(a + 8 * j, v[j]); acc8(a + 8 * j, v[4 + j]); }
        }
        for (; e < s1; e++) {
            const uint4* p0 = (const uint4*)(g_h2 + (size_t)g_colsrc[e] * (cM * cD));
            #pragma unroll
            for (int j = 0; j < 4; j++) acc8(a + 8 * j, p0[4 * lane + j]);
        }
        const uint4* ps = (const uint4*)(g_h2 + (size_t)node * (cM * cD));
        #pragma unroll
        for (int j = 0; j < 4; j++) fma8(a + 8 * j, ps[4 * lane + j], eps2);
        // lane covers elements 32*lane..32*lane+31: m = lane>>1, d0 = (lane&1)*32
        float* zp = zt + (w * 16 + (lane >> 1)) * 65 + (lane & 1) * 32;
        #pragma unroll
        for (int j = 0; j < 32; j++) zp[j] = a[j];
    }
    __syncthreads();

    const int rc = t >> 3, cc = t & 7;
    float acc[4][8];
    #pragma unroll
    for (int i = 0; i < 4; i++)
        #pragma unroll
        for (int q = 0; q < 8; q++) acc[i][q] = 0.f;
    gemm_tile<64, 65>(zt, wa, rc, cc, acc);
    #pragma unroll
    for (int i = 0; i < 4; i++)
        #pragma unroll
        for (int q = 0; q < 8; q++)
            at[(4 * rc + i) * 65 + cc * 8 + q] = fmaxf(acc[i][q] + ba[cc * 8 + q], 0.f);
    __syncthreads();

    float acc2[4][8];
    #pragma unroll
    for (int i = 0; i < 4; i++)
        #pragma unroll
        for (int q = 0; q < 8; q++) acc2[i][q] = 0.f;
    gemm_tile<64, 65>(at, wb, rc, cc, acc2);

    float part[8];
    #pragma unroll
    for (int q = 0; q < 8; q++) {
        float s = 0.f;
        #pragma unroll
        for (int i = 0; i < 4; i++) s += fmaxf(acc2[i][q] + bb[cc * 8 + q], 0.f);
        part[q] = s;
    }
    #pragma unroll
    for (int q = 0; q < 8; q++) {
        part[q] += __shfl_xor_sync(0xffffffffu, part[q], 8);
        part[q] += __shfl_xor_sync(0xffffffffu, part[q], 16);
    }
    if (lane < 8) {
        float4* dst = (float4*)(out + (size_t)node * 64 + cc * 8);
        dst[0] = make_float4(part[0], part[1], part[2], part[3]);
        dst[1] = make_float4(part[4], part[5], part[6], part[7]);
    }
}

// ---------------- launch ----------------
extern "C" void kernel_launch(void* const* d_in, const int* in_sizes, int n_in,
                              void* d_out, int out_size) {
    (void)in_sizes; (void)n_in; (void)out_size;
    const float* lap  = (const float*)d_in[0];
    const float* W0   = (const float*)d_in[1];
    const float* mlpW = (const float*)d_in[2];
    const float* mlpb = (const float*)d_in[3];
    const float* bng  = (const float*)d_in[4];
    const float* bnb  = (const float*)d_in[5];
    const float* eps1 = (const float*)d_in[6];
    const float* W1a  = (const float*)d_in[7];
    const float* b1a  = (const float*)d_in[8];
    const float* W1b  = (const float*)d_in[9];
    const float* b1b  = (const float*)d_in[10];
    const float* eps2 = (const float*)d_in[11];
    const float* W2a  = (const float*)d_in[12];
    const float* b2a  = (const float*)d_in[13];
    const float* W2b  = (const float*)d_in[14];
    const float* b2b  = (const float*)d_in[15];
    const int*   ei   = (const int*)d_in[16];
    float* out = (float*)d_out;

    const int sm1 = (128 * 129 + 2 * 128 * 20) * (int)sizeof(float);
    const int sm3 = (128 * 17 + 128 * 65 + 1024 + 4096 + 128) * (int)sizeof(float);
    const int sm4 = (2 * 128 * 65 + 2 * 4096 + 128) * (int)sizeof(float);
    cudaFuncSetAttribute(k_poly, cudaFuncAttributeMaxDynamicSharedMemorySize, sm1);
    cudaFuncSetAttribute(k_gin1, cudaFuncAttributeMaxDynamicSharedMemorySize, sm3);
    cudaFuncSetAttribute(k_gin2, cudaFuncAttributeMaxDynamicSharedMemorySize, sm4);

    k_poly<<<cB, 512, sm1>>>(lap, W0);
    k_zero<<<(NSUM + 255) / 256, 256>>>();
    k_hist<<<256, 256>>>(ei);
    k_mlpbn<<<cB, 256>>>(mlpW, mlpb, bng, bnb);
    k_scan<<<1, 512>>>();
    k_scatter<<<256, 256>>>(ei);
    k_gin1<<<NSUM / 8, 256, sm3>>>(eps1, W1a, b1a, W1b, b1b);
    k_gin2<<<NSUM / 8, 256, sm4>>>(eps2, W2a, b2a, W2b, b2b, out);
}

// round 11
// speedup vs baseline: 1.6733x; 1.6300x over previous
#include <cuda_runtime.h>
#include <cuda_fp16.h>

#define cB 128
#define cN 128
#define cM 16
#define cK 8
#define cH 16
#define cD 64
#define cE 262144
#define NSUM 16384

// ---------------- device scratch (no allocations allowed) ----------------
__device__ __align__(16) float  g_feat[cB * cK * cN * cM];   // 8 MB
__device__ __align__(16) __half g_h1[NSUM * cM * cH];        // 8.4 MB
__device__ __align__(16) __half g_h2[NSUM * cM * cD];        // 33.5 MB
__device__ int g_cnt[NSUM];
__device__ int g_rowptr[NSUM + 1];
__device__ int g_cursor[NSUM];
__device__ int g_colsrc[cE];

__device__ __forceinline__ void acc8(float* a, uint4 v) {
    const __half2* p = (const __half2*)&v;
    #pragma unroll
    for (int j = 0; j < 4; j++) {
        const float2 f = __half22float2(p[j]);
        a[2 * j] += f.x; a[2 * j + 1] += f.y;
    }
}
__device__ __forceinline__ void fma8(float* a, uint4 v, float s) {
    const __half2* p = (const __half2*)&v;
    #pragma unroll
    for (int j = 0; j < 4; j++) {
        const float2 f = __half22float2(p[j]);
        a[2 * j] = fmaf(s, f.x, a[2 * j]);
        a[2 * j + 1] = fmaf(s, f.y, a[2 * j + 1]);
    }
}
// pack 8 floats into a uint4 of halves
__device__ __forceinline__ uint4 pack8(const float* a) {
    uint4 pk;
    __half2* pp = (__half2*)&pk;
    #pragma unroll
    for (int j = 0; j < 4; j++) pp[j] = __floats2half2_rn(a[2 * j], a[2 * j + 1]);
    return pk;
}

// ---------------- K1: polynomial filter ----------------
__global__ void __launch_bounds__(512) k_poly(const float* __restrict__ lap,
                                              const float* __restrict__ W0) {
    extern __shared__ float sm[];
    float* lapS = sm;                  // [128][129]
    float* buf0 = lapS + 128 * 129;    // [128][20]
    float* buf1 = buf0 + 128 * 20;
    const int b = blockIdx.x;
    const int t = threadIdx.x;

    const float* lapG = lap + (size_t)b * cN * cN;
    for (int i = t; i < cN * cN; i += 512)
        lapS[(i >> 7) * 129 + (i & 127)] = lapG[i];

    const float* w0G = W0 + (size_t)b * cN * cM;
    float* featG = g_feat + (size_t)b * (cK * cN * cM);
    for (int i = t; i < cN * cM; i += 512) {
        float v = w0G[i];
        buf0[(i >> 4) * 20 + (i & 15)] = v;
        featG[i] = v;
    }
    __syncthreads();

    const int n = t >> 2, mg = t & 3;
    float* Wc = buf0;
    float* Wn = buf1;
    const float* lrow = lapS + n * 129;
    for (int k = 1; k < cK; k++) {
        float a0 = 0.f, a1 = 0.f, a2 = 0.f, a3 = 0.f;
        #pragma unroll 8
        for (int j = 0; j < cN; j++) {
            const float l = lrow[j];
            const float4 w = *(const float4*)(Wc + j * 20 + mg * 4);
            a0 = fmaf(l, w.x, a0);
            a1 = fmaf(l, w.y, a1);
            a2 = fmaf(l, w.z, a2);
            a3 = fmaf(l, w.w, a3);
        }
        *(float4*)(Wn + n * 20 + mg * 4) = make_float4(a0, a1, a2, a3);
        ((float4*)(featG + k * (cN * cM)))[t] = make_float4(a0, a1, a2, a3);
        __syncthreads();
        float* tmp = Wc; Wc = Wn; Wn = tmp;
    }
}

// ---------------- K1b: MLP(K->H) + BatchNorm + relu -> g_h1 fp16 ----------------
__global__ void __launch_bounds__(256) k_mlpbn(const float* __restrict__ mlpW,
                                               const float* __restrict__ mlpb,
                                               const float* __restrict__ bng,
                                               const float* __restrict__ bnb) {
    __shared__ float wS[cK * cH];
    __shared__ float bS[cH];
    __shared__ float red[8][32];
    __shared__ float scaleS[cH], shiftS[cH];
    const int b = blockIdx.x, t = threadIdx.x;
    if (t < cK * cH) wS[t] = mlpW[t];
    if (t < cH) bS[t] = mlpb[t];
    __syncthreads();

    const float* fG = g_feat + (size_t)b * (cK * cN * cM);
    float sum[cH], sq[cH];
    #pragma unroll
    for (int c = 0; c < cH; c++) { sum[c] = 0.f; sq[c] = 0.f; }

    for (int r = t; r < cN * cM; r += 256) {
        float f[cK];
        #pragma unroll
        for (int k = 0; k < cK; k++) f[k] = fG[k * (cN * cM) + r];
        #pragma unroll
        for (int c = 0; c < cH; c++) {
            float h = bS[c];
            #pragma unroll
            for (int k = 0; k < cK; k++) h = fmaf(f[k], wS[k * cH + c], h);
            sum[c] += h; sq[c] += h * h;
        }
    }
    #pragma unroll
    for (int c = 0; c < cH; c++)
        for (int o = 16; o; o >>= 1) {
            sum[c] += __shfl_xor_sync(0xffffffffu, sum[c], o);
            sq[c]  += __shfl_xor_sync(0xffffffffu, sq[c],  o);
        }
    const int wid = t >> 5, lane = t & 31;
    if (lane == 0) {
        #pragma unroll
        for (int c = 0; c < cH; c++) { red[wid][c] = sum[c]; red[wid][16 + c] = sq[c]; }
    }
    __syncthreads();
    if (t < 32) {
        float v = 0.f;
        for (int w2 = 0; w2 < 8; w2++) v += red[w2][t];
        red[0][t] = v;
    }
    __syncthreads();
    if (t < cH) {
        const float mu = red[0][t] * (1.f / 2048.f);
        const float var = red[0][16 + t] * (1.f / 2048.f) - mu * mu;
        const float sc = bng[t] * rsqrtf(var + 1e-5f);
        scaleS[t] = sc;
        shiftS[t] = bnb[t] - mu * sc;
    }
    __syncthreads();

    __half* h1G = g_h1 + (size_t)b * (cN * cM * cH);
    for (int r = t; r < cN * cM; r += 256) {
        float f[cK];
        #pragma unroll
        for (int k = 0; k < cK; k++) f[k] = fG[k * (cN * cM) + r];
        float o[cH];
        #pragma unroll
        for (int c = 0; c < cH; c++) {
            float h = bS[c];
            #pragma unroll
            for (int k = 0; k < cK; k++) h = fmaf(f[k], wS[k * cH + c], h);
            o[c] = fmaxf(fmaf(h, scaleS[c], shiftS[c]), 0.f);
        }
        uint4* dst = (uint4*)(h1G + r * cH);
        dst[0] = pack8(o);
        dst[1] = pack8(o + 8);
    }
}

// ---------------- CSR build ----------------
__global__ void k_zero() {
    int i = blockIdx.x * blockDim.x + threadIdx.x;
    if (i < NSUM) g_cnt[i] = 0;
}
__global__ void k_hist(const int* __restrict__ ei) {
    const int stride = gridDim.x * blockDim.x;
    for (int e = blockIdx.x * blockDim.x + threadIdx.x; e < cE; e += stride)
        atomicAdd(&g_cnt[ei[cE + e]], 1);
}
__global__ void __launch_bounds__(512) k_scan() {
    __shared__ int wsum[16], woff[16];
    const int t = threadIdx.x, lane = t & 31, wid = t >> 5;
    const int base = t * 32;
    int s = 0;
    for (int i = 0; i < 32; i++) s += g_cnt[base + i];
    int v = s;
    for (int o = 1; o < 32; o <<= 1) {
        int u = __shfl_up_sync(0xffffffffu, v, o);
        if (lane >= o) v += u;
    }
    if (lane == 31) wsum[wid] = v;
    __syncthreads();
    if (t == 0) {
        int r = 0;
        for (int w2 = 0; w2 < 16; w2++) { woff[w2] = r; r += wsum[w2]; }
    }
    __syncthreads();
    int run = woff[wid] + (v - s);
    for (int i = 0; i < 32; i++) {
        const int c = g_cnt[base + i];
        g_rowptr[base + i] = run;
        g_cursor[base + i] = run;
        run += c;
    }
    if (t == 511) g_rowptr[NSUM] = run;
}
__global__ void k_scatter(const int* __restrict__ ei) {
    const int stride = gridDim.x * blockDim.x;
    for (int e = blockIdx.x * blockDim.x + threadIdx.x; e < cE; e += stride) {
        const int d = ei[cE + e];
        const int p = atomicAdd(&g_cursor[d], 1);
        g_colsrc[p] = ei[e];
    }
}

// ---------------- inline-PTX m16n8k16 HMMA GEMM ----------------
// Warp computes C[16 x 64] = A[16 x 16*KT] (row-major, lda halves) @ Bt^T,
// Bt stored n-major [64][ldb halves] (k contiguous per n == col-major B).
// Result written to cbuf (row-major, ld 68 floats), warp row base passed in.
template <int KT>
__device__ __forceinline__ void mma_gemm(const __half* __restrict__ A, int lda,
                                         const __half* __restrict__ Bt, int ldb,
                                         float* __restrict__ cbuf, int lane) {
    const int g = lane >> 2, tg = lane & 3;
    float c[8][4];
    #pragma unroll
    for (int nt = 0; nt < 8; nt++)
        #pragma unroll
        for (int j = 0; j < 4; j++) c[nt][j] = 0.f;

    #pragma unroll
    for (int kt = 0; kt < KT; kt++) {
        const int k0 = kt * 16 + 2 * tg;
        const unsigned a0 = *(const unsigned*)(A + g * lda + k0);
        const unsigned a1 = *(const unsigned*)(A + (g + 8) * lda + k0);
        const unsigned a2 = *(const unsigned*)(A + g * lda + k0 + 8);
        const unsigned a3 = *(const unsigned*)(A + (g + 8) * lda + k0 + 8);
        #pragma unroll
        for (int nt = 0; nt < 8; nt++) {
            const __half* bp = Bt + (nt * 8 + g) * ldb + k0;
            const unsigned b0 = *(const unsigned*)(bp);
            const unsigned b1 = *(const unsigned*)(bp + 8);
            asm volatile(
                "mma.sync.aligned.m16n8k16.row.col.f32.f16.f16.f32 "
                "{%0,%1,%2,%3}, {%4,%5,%6,%7}, {%8,%9}, {%0,%1,%2,%3};\n"
                : "+f"(c[nt][0]), "+f"(c[nt][1]), "+f"(c[nt][2]), "+f"(c[nt][3])
                : "r"(a0), "r"(a1), "r"(a2), "r"(a3), "r"(b0), "r"(b1));
        }
    }
    // c[nt][0,1] -> (row g, cols nt*8+2tg, +1); c[nt][2,3] -> (row g+8, same cols)
    #pragma unroll
    for (int nt = 0; nt < 8; nt++) {
        *(float2*)(cbuf + g * 68 + nt * 8 + 2 * tg) = make_float2(c[nt][0], c[nt][1]);
        *(float2*)(cbuf + (g + 8) * 68 + nt * 8 + 2 * tg) = make_float2(c[nt][2], c[nt][3]);
    }
}

// bias + relu on cbuf[128][68] -> fp16 dst[128][dstld] (dstld in halves)
__device__ __forceinline__ void bias_relu_h16(const float* cbuf, const float* bias,
                                              __half* dst, int dstld, int t) {
    const int r = t >> 1, c0 = (t & 1) * 32;
    const float* rp = cbuf + r * 68 + c0;
    #pragma unroll
    for (int g = 0; g < 4; g++) {
        float y[8];
        #pragma unroll
        for (int j = 0; j < 8; j++)
            y[j] = fmaxf(rp[g * 8 + j] + bias[c0 + g * 8 + j], 0.f);
        *(uint4*)(dst + r * dstld + c0 + g * 8) = pack8(y);
    }
}

// ---------------- K3: fused GIN layer 1 (agg fp16 16-dim + HMMA 16->64->64) -> g_h2 fp16 ----------------
__global__ void __launch_bounds__(256) k_gin1(const float* __restrict__ eps1p,
                                              const float* __restrict__ W1a,
                                              const float* __restrict__ b1a,
                                              const float* __restrict__ W1b,
                                              const float* __restrict__ b1b) {
    extern __shared__ char smraw[];
    float*  cbuf = (float*)smraw;              // [128][68]
    float*  ba   = cbuf + 128 * 68;            // 64
    float*  bb   = ba + 64;                    // 64
    __half* zt   = (__half*)(bb + 64);         // [128][24]
    __half* at   = zt + 128 * 24;              // [128][72]
    __half* wta  = at + 128 * 72;              // [64][24]  (n-major, k inner)
    __half* wtb  = wta + 64 * 24;              // [64][72]
    const int t = threadIdx.x, blk = blockIdx.x;

    for (int i = t; i < 1024; i += 256) {
        const int k = i >> 6, n = i & 63;
        wta[n * 24 + k] = __float2half(W1a[i]);
    }
    for (int i = t; i < 4096; i += 256) {
        const int k = i >> 6, n = i & 63;
        wtb[n * 72 + k] = __float2half(W1b[i]);
    }
    if (t < 64) { ba[t] = b1a[t]; bb[t] = b1b[t]; }

    const float eps1 = 1.f + eps1p[0];
    const int w = t >> 5, lane = t & 31;
    const int node = blk * 8 + w;
    {
        float a[8];
        #pragma unroll
        for (int j = 0; j < 8; j++) a[j] = 0.f;
        const int s0 = g_rowptr[node], s1 = g_rowptr[node + 1];
        int e = s0;
        for (; e + 4 <= s1; e += 4) {
            const int c0 = g_colsrc[e], c1 = g_colsrc[e + 1];
            const int c2 = g_colsrc[e + 2], c3 = g_colsrc[e + 3];
            const uint4 v0 = ((const uint4*)(g_h1 + c0 * (cM * cH)))[lane];
            const uint4 v1 = ((const uint4*)(g_h1 + c1 * (cM * cH)))[lane];
            const uint4 v2 = ((const uint4*)(g_h1 + c2 * (cM * cH)))[lane];
            const uint4 v3 = ((const uint4*)(g_h1 + c3 * (cM * cH)))[lane];
            acc8(a, v0); acc8(a, v1); acc8(a, v2); acc8(a, v3);
        }
        for (; e < s1; e++) {
            const uint4 v = ((const uint4*)(g_h1 + g_colsrc[e] * (cM * cH)))[lane];
            acc8(a, v);
        }
        const uint4 vs = ((const uint4*)(g_h1 + node * (cM * cH)))[lane];
        fma8(a, vs, eps1);
        // lane covers elements 8*lane..8*lane+7: m = lane>>1, c0 = (lane&1)*8
        *(uint4*)(zt + (w * 16 + (lane >> 1)) * 24 + (lane & 1) * 8) = pack8(a);
    }
    __syncthreads();

    mma_gemm<1>(zt + w * 16 * 24, 24, wta, 24, cbuf + w * 16 * 68, lane);
    __syncthreads();
    bias_relu_h16(cbuf, ba, at, 72, t);
    __syncthreads();

    mma_gemm<4>(at + w * 16 * 72, 72, wtb, 72, cbuf + w * 16 * 68, lane);
    __syncthreads();
    // bias + relu -> fp16 -> g_h2
    bias_relu_h16(cbuf, bb, g_h2 + (size_t)(blk * 128) * cD, cD, t);
}

// ---------------- K4: fused GIN layer 2 (agg fp16 64-dim + HMMA 64->64->64 + m-sum) -> out ----------------
__global__ void __launch_bounds__(256) k_gin2(const float* __restrict__ eps2p,
                                              const float* __restrict__ W2a,
                                              const float* __restrict__ b2a,
                                              const float* __restrict__ W2b,
                                              const float* __restrict__ b2b,
                                              float* __restrict__ out) {
    extern __shared__ char smraw[];
    float*  cbuf = (float*)smraw;              // [128][68]
    float*  ba   = cbuf + 128 * 68;
    float*  bb   = ba + 64;
    __half* zt   = (__half*)(bb + 64);         // [128][72]
    __half* at   = zt + 128 * 72;              // [128][72]
    __half* wta  = at + 128 * 72;              // [64][72]
    __half* wtb  = wta + 64 * 72;              // [64][72]
    const int t = threadIdx.x, blk = blockIdx.x;

    for (int i = t; i < 4096; i += 256) {
        const int k = i >> 6, n = i & 63;
        wta[n * 72 + k] = __float2half(W2a[i]);
        wtb[n * 72 + k] = __float2half(W2b[i]);
    }
    if (t < 64) { ba[t] = b2a[t]; bb[t] = b2b[t]; }

    const float eps2 = 1.f + eps2p[0];
    const int w = t >> 5, lane = t & 31;
    const int node = blk * 8 + w;
    {
        float a[32];
        #pragma unroll
        for (int j = 0; j < 32; j++) a[j] = 0.f;
        const int s0 = g_rowptr[node], s1 = g_rowptr[node + 1];
        int e = s0;
        for (; e + 2 <= s1; e += 2) {
            const uint4* p0 = (const uint4*)(g_h2 + (size_t)g_colsrc[e] * (cM * cD));
            const uint4* p1 = (const uint4*)(g_h2 + (size_t)g_colsrc[e + 1] * (cM * cD));
            uint4 v[8];
            #pragma unroll
            for (int j = 0; j < 4; j++) v[j] = p0[4 * lane + j];
            #pragma unroll
            for (int j = 0; j < 4; j++) v[4 + j] = p1[4 * lane + j];
            #pragma unroll
            for (int j = 0; j < 4; j++) { acc8(a + 8 * j, v[j]); acc8(a + 8 * j, v[4 + j]); }
        }
        for (; e < s1; e++) {
            const uint4* p0 = (const uint4*)(g_h2 + (size_t)g_colsrc[e] * (cM * cD));
            #pragma unroll
            for (int j = 0; j < 4; j++) acc8(a + 8 * j, p0[4 * lane + j]);
        }
        const uint4* ps = (const uint4*)(g_h2 + (size_t)node * (cM * cD));
        #pragma unroll
        for (int j = 0; j < 4; j++) fma8(a + 8 * j, ps[4 * lane + j], eps2);
        // lane covers 32 elements: m = lane>>1, d0 = (lane&1)*32
        __half* zp = zt + (w * 16 + (lane >> 1)) * 72 + (lane & 1) * 32;
        #pragma unroll
        for (int j = 0; j < 4; j++) *(uint4*)(zp + j * 8) = pack8(a + 8 * j);
    }
    __syncthreads();

    mma_gemm<4>(zt + w * 16 * 72, 72, wta, 72, cbuf + w * 16 * 68, lane);
    __syncthreads();
    bias_relu_h16(cbuf, ba, at, 72, t);
    __syncthreads();

    mma_gemm<4>(at + w * 16 * 72, 72, wtb, 72, cbuf + w * 16 * 68, lane);
    __syncthreads();

    // bias + relu + sum over m (16 rows per node) -> out fp32
    const int nl = t >> 5, ln = t & 31;
    float s0 = 0.f, s1 = 0.f;
    const float b0 = bb[ln], b1 = bb[ln + 32];
    #pragma unroll
    for (int m = 0; m < 16; m++) {
        const float* rp = cbuf + (nl * 16 + m) * 68;
        s0 += fmaxf(rp[ln] + b0, 0.f);
        s1 += fmaxf(rp[ln + 32] + b1, 0.f);
    }
    float* op = out + (size_t)(blk * 8 + nl) * 64;
    op[ln] = s0;
    op[ln + 32] = s1;
}

// ---------------- launch ----------------
extern "C" void kernel_launch(void* const* d_in, const int* in_sizes, int n_in,
                              void* d_out, int out_size) {
    (void)in_sizes; (void)n_in; (void)out_size;
    const float* lap  = (const float*)d_in[0];
    const float* W0   = (const float*)d_in[1];
    const float* mlpW = (const float*)d_in[2];
    const float* mlpb = (const float*)d_in[3];
    const float* bng  = (const float*)d_in[4];
    const float* bnb  = (const float*)d_in[5];
    const float* eps1 = (const float*)d_in[6];
    const float* W1a  = (const float*)d_in[7];
    const float* b1a  = (const float*)d_in[8];
    const float* W1b  = (const float*)d_in[9];
    const float* b1b  = (const float*)d_in[10];
    const float* eps2 = (const float*)d_in[11];
    const float* W2a  = (const float*)d_in[12];
    const float* b2a  = (const float*)d_in[13];
    const float* W2b  = (const float*)d_in[14];
    const float* b2b  = (const float*)d_in[15];
    const int*   ei   = (const int*)d_in[16];
    float* out = (float*)d_out;

    const int sm1 = (128 * 129 + 2 * 128 * 20) * (int)sizeof(float);
    const int sm3 = (128 * 68 + 128) * 4 + (128 * 24 + 128 * 72 + 64 * 24 + 64 * 72) * 2;   // 72,192 B
    const int sm4 = (128 * 68 + 128) * 4 + (2 * 128 * 72 + 2 * 64 * 72) * 2;                // 90,624 B
    cudaFuncSetAttribute(k_poly, cudaFuncAttributeMaxDynamicSharedMemorySize, sm1);
    cudaFuncSetAttribute(k_gin1, cudaFuncAttributeMaxDynamicSharedMemorySize, sm3);
    cudaFuncSetAttribute(k_gin2, cudaFuncAttributeMaxDynamicSharedMemorySize, sm4);

    k_poly<<<cB, 512, sm1>>>(lap, W0);
    k_zero<<<(NSUM + 255) / 256, 256>>>();
    k_hist<<<256, 256>>>(ei);
    k_mlpbn<<<cB, 256>>>(mlpW, mlpb, bng, bnb);
    k_scan<<<1, 512>>>();
    k_scatter<<<256, 256>>>(ei);
    k_gin1<<<NSUM / 8, 256, sm3>>>(eps1, W1a, b1a, W1b, b1b);
    k_gin2<<<NSUM / 8, 256, sm4>>>(eps2, W2a, b2a, W2b, b2b, out);
}

// round 13
// speedup vs baseline: 1.9067x; 1.1394x over previous
#include <cuda_runtime.h>
#include <cuda_fp16.h>

#define cB 128
#define cN 128
#define cM 16
#define cK 8
#define cH 16
#define cD 64
#define cE 262144
#define NSUM 16384

// ---------------- device scratch (no allocations allowed) ----------------
__device__ __align__(16) float  g_feat[cB * cK * cN * cM];   // 8 MB
__device__ __align__(16) __half g_h1[NSUM * cM * cH];        // 8.4 MB
__device__ __align__(16) __half g_h2[NSUM * cM * cD];        // 33.5 MB
__device__ int g_cnt[NSUM];
__device__ int g_rowptr[NSUM + 1];
__device__ int g_cursor[NSUM];
__device__ int g_colsrc[cE];

__device__ __forceinline__ void acc8(float* a, uint4 v) {
    const __half2* p = (const __half2*)&v;
    #pragma unroll
    for (int j = 0; j < 4; j++) {
        const float2 f = __half22float2(p[j]);
        a[2 * j] += f.x; a[2 * j + 1] += f.y;
    }
}
__device__ __forceinline__ void fma8(float* a, uint4 v, float s) {
    const __half2* p = (const __half2*)&v;
    #pragma unroll
    for (int j = 0; j < 4; j++) {
        const float2 f = __half22float2(p[j]);
        a[2 * j] = fmaf(s, f.x, a[2 * j]);
        a[2 * j + 1] = fmaf(s, f.y, a[2 * j + 1]);
    }
}
// pack 8 floats into a uint4 of halves
__device__ __forceinline__ uint4 pack8(const float* a) {
    uint4 pk;
    __half2* pp = (__half2*)&pk;
    #pragma unroll
    for (int j = 0; j < 4; j++) pp[j] = __floats2half2_rn(a[2 * j], a[2 * j + 1]);
    return pk;
}

// ---------------- K1: polynomial filter ----------------
__global__ void __launch_bounds__(512) k_poly(const float* __restrict__ lap,
                                              const float* __restrict__ W0) {
    extern __shared__ float sm[];
    float* lapS = sm;                  // [128][129]
    float* buf0 = lapS + 128 * 129;    // [128][20]
    float* buf1 = buf0 + 128 * 20;
    const int b = blockIdx.x;
    const int t = threadIdx.x;

    const float* lapG = lap + (size_t)b * cN * cN;
    for (int i = t; i < cN * cN; i += 512)
        lapS[(i >> 7) * 129 + (i & 127)] = lapG[i];

    const float* w0G = W0 + (size_t)b * cN * cM;
    float* featG = g_feat + (size_t)b * (cK * cN * cM);
    for (int i = t; i < cN * cM; i += 512) {
        float v = w0G[i];
        buf0[(i >> 4) * 20 + (i & 15)] = v;
        featG[i] = v;
    }
    __syncthreads();

    const int n = t >> 2, mg = t & 3;
    float* Wc = buf0;
    float* Wn = buf1;
    const float* lrow = lapS + n * 129;
    for (int k = 1; k < cK; k++) {
        float a0 = 0.f, a1 = 0.f, a2 = 0.f, a3 = 0.f;
        #pragma unroll 8
        for (int j = 0; j < cN; j++) {
            const float l = lrow[j];
            const float4 w = *(const float4*)(Wc + j * 20 + mg * 4);
            a0 = fmaf(l, w.x, a0);
            a1 = fmaf(l, w.y, a1);
            a2 = fmaf(l, w.z, a2);
            a3 = fmaf(l, w.w, a3);
        }
        *(float4*)(Wn + n * 20 + mg * 4) = make_float4(a0, a1, a2, a3);
        ((float4*)(featG + k * (cN * cM)))[t] = make_float4(a0, a1, a2, a3);
        __syncthreads();
        float* tmp = Wc; Wc = Wn; Wn = tmp;
    }
}

// ---------------- K1b: MLP(K->H) + BatchNorm + relu -> g_h1 fp16 ----------------
__global__ void __launch_bounds__(256) k_mlpbn(const float* __restrict__ mlpW,
                                               const float* __restrict__ mlpb,
                                               const float* __restrict__ bng,
                                               const float* __restrict__ bnb) {
    __shared__ float wS[cK * cH];
    __shared__ float bS[cH];
    __shared__ float red[8][32];
    __shared__ float scaleS[cH], shiftS[cH];
    const int b = blockIdx.x, t = threadIdx.x;
    if (t < cK * cH) wS[t] = mlpW[t];
    if (t < cH) bS[t] = mlpb[t];
    __syncthreads();

    const float* fG = g_feat + (size_t)b * (cK * cN * cM);
    float sum[cH], sq[cH];
    #pragma unroll
    for (int c = 0; c < cH; c++) { sum[c] = 0.f; sq[c] = 0.f; }

    for (int r = t; r < cN * cM; r += 256) {
        float f[cK];
        #pragma unroll
        for (int k = 0; k < cK; k++) f[k] = fG[k * (cN * cM) + r];
        #pragma unroll
        for (int c = 0; c < cH; c++) {
            float h = bS[c];
            #pragma unroll
            for (int k = 0; k < cK; k++) h = fmaf(f[k], wS[k * cH + c], h);
            sum[c] += h; sq[c] += h * h;
        }
    }
    #pragma unroll
    for (int c = 0; c < cH; c++)
        for (int o = 16; o; o >>= 1) {
            sum[c] += __shfl_xor_sync(0xffffffffu, sum[c], o);
            sq[c]  += __shfl_xor_sync(0xffffffffu, sq[c],  o);
        }
    const int wid = t >> 5, lane = t & 31;
    if (lane == 0) {
        #pragma unroll
        for (int c = 0; c < cH; c++) { red[wid][c] = sum[c]; red[wid][16 + c] = sq[c]; }
    }
    __syncthreads();
    if (t < 32) {
        float v = 0.f;
        for (int w2 = 0; w2 < 8; w2++) v += red[w2][t];
        red[0][t] = v;
    }
    __syncthreads();
    if (t < cH) {
        const float mu = red[0][t] * (1.f / 2048.f);
        const float var = red[0][16 + t] * (1.f / 2048.f) - mu * mu;
        const float sc = bng[t] * rsqrtf(var + 1e-5f);
        scaleS[t] = sc;
        shiftS[t] = bnb[t] - mu * sc;
    }
    __syncthreads();

    __half* h1G = g_h1 + (size_t)b * (cN * cM * cH);
    for (int r = t; r < cN * cM; r += 256) {
        float f[cK];
        #pragma unroll
        for (int k = 0; k < cK; k++) f[k] = fG[k * (cN * cM) + r];
        float o[cH];
        #pragma unroll
        for (int c = 0; c < cH; c++) {
            float h = bS[c];
            #pragma unroll
            for (int k = 0; k < cK; k++) h = fmaf(f[k], wS[k * cH + c], h);
            o[c] = fmaxf(fmaf(h, scaleS[c], shiftS[c]), 0.f);
        }
        uint4* dst = (uint4*)(h1G + r * cH);
        dst[0] = pack8(o);
        dst[1] = pack8(o + 8);
    }
}

// ---------------- CSR build ----------------
__global__ void k_zero() {
    int i = blockIdx.x * blockDim.x + threadIdx.x;
    if (i < NSUM) g_cnt[i] = 0;
}
__global__ void k_hist(const int* __restrict__ ei) {
    const int stride = gridDim.x * blockDim.x;
    for (int e = blockIdx.x * blockDim.x + threadIdx.x; e < cE; e += stride)
        atomicAdd(&g_cnt[ei[cE + e]], 1);
}
__global__ void __launch_bounds__(512) k_scan() {
    __shared__ int wsum[16], woff[16];
    const int t = threadIdx.x, lane = t & 31, wid = t >> 5;
    const int base = t * 32;
    int s = 0;
    for (int i = 0; i < 32; i++) s += g_cnt[base + i];
    int v = s;
    for (int o = 1; o < 32; o <<= 1) {
        int u = __shfl_up_sync(0xffffffffu, v, o);
        if (lane >= o) v += u;
    }
    if (lane == 31) wsum[wid] = v;
    __syncthreads();
    if (t == 0) {
        int r = 0;
        for (int w2 = 0; w2 < 16; w2++) { woff[w2] = r; r += wsum[w2]; }
    }
    __syncthreads();
    int run = woff[wid] + (v - s);
    for (int i = 0; i < 32; i++) {
        const int c = g_cnt[base + i];
        g_rowptr[base + i] = run;
        g_cursor[base + i] = run;
        run += c;
    }
    if (t == 511) g_rowptr[NSUM] = run;
}
__global__ void k_scatter(const int* __restrict__ ei) {
    const int stride = gridDim.x * blockDim.x;
    for (int e = blockIdx.x * blockDim.x + threadIdx.x; e < cE; e += stride) {
        const int d = ei[cE + e];
        const int p = atomicAdd(&g_cursor[d], 1);
        g_colsrc[p] = ei[e];
    }
}

// ---------------- inline-PTX m16n8k16 HMMA accumulate ----------------
// Accumulates C[16 x 64] += A[16 x 16*KT] (row-major, lda halves) @ Bt^T into c[8][4].
// Bt stored n-major [64][ldb halves] (k contiguous per n == col-major B).
// Fragment map: c[nt][0,1] -> (row g, cols nt*8+2tg,+1); c[nt][2,3] -> (row g+8, same).
template <int KT>
__device__ __forceinline__ void mma_accum(const __half* __restrict__ A, int lda,
                                          const __half* __restrict__ Bt, int ldb,
                                          int lane, float c[8][4]) {
    const int g = lane >> 2, tg = lane & 3;
    #pragma unroll
    for (int kt = 0; kt < KT; kt++) {
        const int k0 = kt * 16 + 2 * tg;
        const unsigned a0 = *(const unsigned*)(A + g * lda + k0);
        const unsigned a1 = *(const unsigned*)(A + (g + 8) * lda + k0);
        const unsigned a2 = *(const unsigned*)(A + g * lda + k0 + 8);
        const unsigned a3 = *(const unsigned*)(A + (g + 8) * lda + k0 + 8);
        #pragma unroll
        for (int nt = 0; nt < 8; nt++) {
            const __half* bp = Bt + (nt * 8 + g) * ldb + k0;
            const unsigned b0 = *(const unsigned*)(bp);
            const unsigned b1 = *(const unsigned*)(bp + 8);
            asm volatile(
                "mma.sync.aligned.m16n8k16.row.col.f32.f16.f16.f32 "
                "{%0,%1,%2,%3}, {%4,%5,%6,%7}, {%8,%9}, {%0,%1,%2,%3};\n"
                : "+f"(c[nt][0]), "+f"(c[nt][1]), "+f"(c[nt][2]), "+f"(c[nt][3])
                : "r"(a0), "r"(a1), "r"(a2), "r"(a3), "r"(b0), "r"(b1));
        }
    }
}

// ---------------- K3: fused GIN layer 1 (warp-synchronous after weight load) ----------------
__global__ void __launch_bounds__(256) k_gin1(const float* __restrict__ eps1p,
                                              const float* __restrict__ W1a,
                                              const float* __restrict__ b1a,
                                              const float* __restrict__ W1b,
                                              const float* __restrict__ b1b) {
    extern __shared__ char smraw[];
    float*  ba  = (float*)smraw;               // 64
    float*  bb  = ba + 64;                     // 64
    __half* zt  = (__half*)(bb + 64);          // [128][24]
    __half* at  = zt + 128 * 24;               // [128][72]
    __half* wta = at + 128 * 72;               // [64][24]  n-major, k inner
    __half* wtb = wta + 64 * 24;               // [64][72]
    const int t = threadIdx.x, blk = blockIdx.x;

    for (int i = t; i < 1024; i += 256) {
        const int k = i >> 6, n = i & 63;
        wta[n * 24 + k] = __float2half(W1a[i]);
    }
    for (int i = t; i < 4096; i += 256) {
        const int k = i >> 6, n = i & 63;
        wtb[n * 72 + k] = __float2half(W1b[i]);
    }
    if (t < 64) { ba[t] = b1a[t]; bb[t] = b1b[t]; }
    const float eps1 = 1.f + eps1p[0];
    __syncthreads();   // the ONLY block sync: weights/biases visible to all warps

    const int w = t >> 5, lane = t & 31;
    const int node = blk * 8 + w;
    {
        float a[8];
        #pragma unroll
        for (int j = 0; j < 8; j++) a[j] = 0.f;
        const int s0 = g_rowptr[node], s1 = g_rowptr[node + 1];
        int e = s0;
        for (; e + 4 <= s1; e += 4) {
            const int c0 = g_colsrc[e], c1 = g_colsrc[e + 1];
            const int c2 = g_colsrc[e + 2], c3 = g_colsrc[e + 3];
            const uint4 v0 = ((const uint4*)(g_h1 + c0 * (cM * cH)))[lane];
            const uint4 v1 = ((const uint4*)(g_h1 + c1 * (cM * cH)))[lane];
            const uint4 v2 = ((const uint4*)(g_h1 + c2 * (cM * cH)))[lane];
            const uint4 v3 = ((const uint4*)(g_h1 + c3 * (cM * cH)))[lane];
            acc8(a, v0); acc8(a, v1); acc8(a, v2); acc8(a, v3);
        }
        for (; e < s1; e++) {
            const uint4 v = ((const uint4*)(g_h1 + g_colsrc[e] * (cM * cH)))[lane];
            acc8(a, v);
        }
        const uint4 vs = ((const uint4*)(g_h1 + node * (cM * cH)))[lane];
        fma8(a, vs, eps1);
        // lane covers elements 8*lane..8*lane+7: m = lane>>1, c0 = (lane&1)*8
        *(uint4*)(zt + (w * 16 + (lane >> 1)) * 24 + (lane & 1) * 8) = pack8(a);
    }
    __syncwarp();

    const int g = lane >> 2, tg = lane & 3;
    // GEMM1: z @ W1a  (K=16)
    float c1[8][4];
    #pragma unroll
    for (int nt = 0; nt < 8; nt++)
        #pragma unroll
        for (int j = 0; j < 4; j++) c1[nt][j] = 0.f;
    mma_accum<1>(zt + w * 16 * 24, 24, wta, 24, lane, c1);
    // bias+relu+pack in registers -> at (own warp's rows only)
    #pragma unroll
    for (int nt = 0; nt < 8; nt++) {
        const int col = nt * 8 + 2 * tg;
        const float2 b = *(const float2*)(ba + col);
        *(__half2*)(at + (w * 16 + g) * 72 + col) =
            __floats2half2_rn(fmaxf(c1[nt][0] + b.x, 0.f), fmaxf(c1[nt][1] + b.y, 0.f));
        *(__half2*)(at + (w * 16 + g + 8) * 72 + col) =
            __floats2half2_rn(fmaxf(c1[nt][2] + b.x, 0.f), fmaxf(c1[nt][3] + b.y, 0.f));
    }
    __syncwarp();

    // GEMM2: a @ W1b  (K=64)
    float c2[8][4];
    #pragma unroll
    for (int nt = 0; nt < 8; nt++)
        #pragma unroll
        for (int j = 0; j < 4; j++) c2[nt][j] = 0.f;
    mma_accum<4>(at + w * 16 * 72, 72, wtb, 72, lane, c2);
    // bias+relu+pack -> g_h2 directly from registers
    __half* outG = g_h2 + (size_t)(blk * 128 + w * 16) * cD;
    #pragma unroll
    for (int nt = 0; nt < 8; nt++) {
        const int col = nt * 8 + 2 * tg;
        const float2 b = *(const float2*)(bb + col);
        *(__half2*)(outG + g * cD + col) =
            __floats2half2_rn(fmaxf(c2[nt][0] + b.x, 0.f), fmaxf(c2[nt][1] + b.y, 0.f));
        *(__half2*)(outG + (g + 8) * cD + col) =
            __floats2half2_rn(fmaxf(c2[nt][2] + b.x, 0.f), fmaxf(c2[nt][3] + b.y, 0.f));
    }
}

// ---------------- K4: fused GIN layer 2 (warp-synchronous, m-sum in registers) ----------------
__global__ void __launch_bounds__(256) k_gin2(const float* __restrict__ eps2p,
                                              const float* __restrict__ W2a,
                                              const float* __restrict__ b2a,
                                              const float* __restrict__ W2b,
                                              const float* __restrict__ b2b,
                                              float* __restrict__ out) {
    extern __shared__ char smraw[];
    float*  ba  = (float*)smraw;               // 64
    float*  bb  = ba + 64;                     // 64
    __half* zt  = (__half*)(bb + 64);          // [128][72]
    __half* at  = zt + 128 * 72;               // [128][72]
    __half* wta = at + 128 * 72;               // [64][72]
    __half* wtb = wta + 64 * 72;               // [64][72]
    const int t = threadIdx.x, blk = blockIdx.x;

    for (int i = t; i < 4096; i += 256) {
        const int k = i >> 6, n = i & 63;
        wta[n * 72 + k] = __float2half(W2a[i]);
        wtb[n * 72 + k] = __float2half(W2b[i]);
    }
    if (t < 64) { ba[t] = b2a[t]; bb[t] = b2b[t]; }
    const float eps2 = 1.f + eps2p[0];
    __syncthreads();   // the ONLY block sync

    const int w = t >> 5, lane = t & 31;
    const int node = blk * 8 + w;
    {
        float a[32];
        #pragma unroll
        for (int j = 0; j < 32; j++) a[j] = 0.f;
        const int s0 = g_rowptr[node], s1 = g_rowptr[node + 1];
        int e = s0;
        for (; e + 2 <= s1; e += 2) {
            const uint4* p0 = (const uint4*)(g_h2 + (size_t)g_colsrc[e] * (cM * cD));
            const uint4* p1 = (const uint4*)(g_h2 + (size_t)g_colsrc[e + 1] * (cM * cD));
            uint4 v[8];
            #pragma unroll
            for (int j = 0; j < 4; j++) v[j] = p0[4 * lane + j];
            #pragma unroll
            for (int j = 0; j < 4; j++) v[4 + j] = p1[4 * lane + j];
            #pragma unroll
            for (int j = 0; j < 4; j++) { acc8(a + 8 * j, v[j]); acc8(a + 8 * j, v[4 + j]); }
        }
        for (; e < s1; e++) {
            const uint4* p0 = (const uint4*)(g_h2 + (size_t)g_colsrc[e] * (cM * cD));
            #pragma unroll
            for (int j = 0; j < 4; j++) acc8(a + 8 * j, p0[4 * lane + j]);
        }
        const uint4* ps = (const uint4*)(g_h2 + (size_t)node * (cM * cD));
        #pragma unroll
        for (int j = 0; j < 4; j++) fma8(a + 8 * j, ps[4 * lane + j], eps2);
        // lane covers 32 elements: m = lane>>1, d0 = (lane&1)*32
        __half* zp = zt + (w * 16 + (lane >> 1)) * 72 + (lane & 1) * 32;
        #pragma unroll
        for (int j = 0; j < 4; j++) *(uint4*)(zp + j * 8) = pack8(a + 8 * j);
    }
    __syncwarp();

    const int g = lane >> 2, tg = lane & 3;
    // GEMM1: z @ W2a  (K=64)
    float c1[8][4];
    #pragma unroll
    for (int nt = 0; nt < 8; nt++)
        #pragma unroll
        for (int j = 0; j < 4; j++) c1[nt][j] = 0.f;
    mma_accum<4>(zt + w * 16 * 72, 72, wta, 72, lane, c1);
    #pragma unroll
    for (int nt = 0; nt < 8; nt++) {
        const int col = nt * 8 + 2 * tg;
        const float2 b = *(const float2*)(ba + col);
        *(__half2*)(at + (w * 16 + g) * 72 + col) =
            __floats2half2_rn(fmaxf(c1[nt][0] + b.x, 0.f), fmaxf(c1[nt][1] + b.y, 0.f));
        *(__half2*)(at + (w * 16 + g + 8) * 72 + col) =
            __floats2half2_rn(fmaxf(c1[nt][2] + b.x, 0.f), fmaxf(c1[nt][3] + b.y, 0.f));
    }
    __syncwarp();

    // GEMM2: a @ W2b  (K=64)
    float c2[8][4];
    #pragma unroll
    for (int nt = 0; nt < 8; nt++)
        #pragma unroll
        for (int j = 0; j < 4; j++) c2[nt][j] = 0.f;
    mma_accum<4>(at + w * 16 * 72, 72, wtb, 72, lane, c2);

    // bias + relu + m-sum fully in registers/shuffles:
    // rows g and g+8 live in this lane; remaining 8 g-values via 3 shfl_xor.
    #pragma unroll
    for (int nt = 0; nt < 8; nt++) {
        const int col = nt * 8 + 2 * tg;
        const float2 b = *(const float2*)(bb + col);
        float s0 = fmaxf(c2[nt][0] + b.x, 0.f) + fmaxf(c2[nt][2] + b.x, 0.f);
        float s1 = fmaxf(c2[nt][1] + b.y, 0.f) + fmaxf(c2[nt][3] + b.y, 0.f);
        #pragma unroll
        for (int o = 4; o <= 16; o <<= 1) {
            s0 += __shfl_xor_sync(0xffffffffu, s0, o);
            s1 += __shfl_xor_sync(0xffffffffu, s1, o);
        }
        if (g == 0)
            *(float2*)(out + (size_t)node * 64 + col) = make_float2(s0, s1);
    }
}

// ---------------- launch ----------------
extern "C" void kernel_launch(void* const* d_in, const int* in_sizes, int n_in,
                              void* d_out, int out_size) {
    (void)in_sizes; (void)n_in; (void)out_size;
    const float* lap  = (const float*)d_in[0];
    const float* W0   = (const float*)d_in[1];
    const float* mlpW = (const float*)d_in[2];
    const float* mlpb = (const float*)d_in[3];
    const float* bng  = (const float*)d_in[4];
    const float* bnb  = (const float*)d_in[5];
    const float* eps1 = (const float*)d_in[6];
    const float* W1a  = (const float*)d_in[7];
    const float* b1a  = (const float*)d_in[8];
    const float* W1b  = (const float*)d_in[9];
    const float* b1b  = (const float*)d_in[10];
    const float* eps2 = (const float*)d_in[11];
    const float* W2a  = (const float*)d_in[12];
    const float* b2a  = (const float*)d_in[13];
    const float* W2b  = (const float*)d_in[14];
    const float* b2b  = (const float*)d_in[15];
    const int*   ei   = (const int*)d_in[16];
    float* out = (float*)d_out;

    const int sm1 = (128 * 129 + 2 * 128 * 20) * (int)sizeof(float);
    const int sm3 = 128 * 4 + (128 * 24 + 128 * 72 + 64 * 24 + 64 * 72) * 2;   // 37,376 B
    const int sm4 = 128 * 4 + (2 * 128 * 72 + 2 * 64 * 72) * 2;                // 55,808 B
    cudaFuncSetAttribute(k_poly, cudaFuncAttributeMaxDynamicSharedMemorySize, sm1);
    cudaFuncSetAttribute(k_gin1, cudaFuncAttributeMaxDynamicSharedMemorySize, sm3);
    cudaFuncSetAttribute(k_gin2, cudaFuncAttributeMaxDynamicSharedMemorySize, sm4);

    k_poly<<<cB, 512, sm1>>>(lap, W0);
    k_zero<<<(NSUM + 255) / 256, 256>>>();
    k_hist<<<256, 256>>>(ei);
    k_mlpbn<<<cB, 256>>>(mlpW, mlpb, bng, bnb);
    k_scan<<<1, 512>>>();
    k_scatter<<<256, 256>>>(ei);
    k_gin1<<<NSUM / 8, 256, sm3>>>(eps1, W1a, b1a, W1b, b1b);
    k_gin2<<<NSUM / 8, 256, sm4>>>(eps2, W2a, b2a, W2b, b2b, out);
}

// round 14
// speedup vs baseline: 1.9893x; 1.0433x over previous
#include <cuda_runtime.h>
#include <cuda_fp16.h>

#define cB 128
#define cN 128
#define cM 16
#define cK 8
#define cH 16
#define cD 64
#define cE 262144
#define NSUM 16384

// ---------------- device scratch (no allocations allowed) ----------------
__device__ __align__(16) float  g_feat[cB * cK * cN * cM];   // 8 MB
__device__ __align__(16) __half g_h1[NSUM * cM * cH];        // 8.4 MB
__device__ __align__(16) __half g_h2[NSUM * cM * cD];        // 33.5 MB
__device__ int g_cnt[NSUM];
__device__ int g_rowptr[NSUM + 1];
__device__ int g_cursor[NSUM];
__device__ int g_colsrc[cE];

__device__ __forceinline__ void acc8(float* a, uint4 v) {
    const __half2* p = (const __half2*)&v;
    #pragma unroll
    for (int j = 0; j < 4; j++) {
        const float2 f = __half22float2(p[j]);
        a[2 * j] += f.x; a[2 * j + 1] += f.y;
    }
}
__device__ __forceinline__ void fma8(float* a, uint4 v, float s) {
    const __half2* p = (const __half2*)&v;
    #pragma unroll
    for (int j = 0; j < 4; j++) {
        const float2 f = __half22float2(p[j]);
        a[2 * j] = fmaf(s, f.x, a[2 * j]);
        a[2 * j + 1] = fmaf(s, f.y, a[2 * j + 1]);
    }
}
// pack 8 floats into a uint4 of halves
__device__ __forceinline__ uint4 pack8(const float* a) {
    uint4 pk;
    __half2* pp = (__half2*)&pk;
    #pragma unroll
    for (int j = 0; j < 4; j++) pp[j] = __floats2half2_rn(a[2 * j], a[2 * j + 1]);
    return pk;
}

// ---------------- K1: polynomial filter ----------------
__global__ void __launch_bounds__(512) k_poly(const float* __restrict__ lap,
                                              const float* __restrict__ W0) {
    extern __shared__ float sm[];
    float* lapS = sm;                  // [128][129]
    float* buf0 = lapS + 128 * 129;    // [128][20]
    float* buf1 = buf0 + 128 * 20;
    const int b = blockIdx.x;
    const int t = threadIdx.x;

    const float* lapG = lap + (size_t)b * cN * cN;
    for (int i = t; i < cN * cN; i += 512)
        lapS[(i >> 7) * 129 + (i & 127)] = lapG[i];

    const float* w0G = W0 + (size_t)b * cN * cM;
    float* featG = g_feat + (size_t)b * (cK * cN * cM);
    for (int i = t; i < cN * cM; i += 512) {
        float v = w0G[i];
        buf0[(i >> 4) * 20 + (i & 15)] = v;
        featG[i] = v;
    }
    __syncthreads();

    const int n = t >> 2, mg = t & 3;
    float* Wc = buf0;
    float* Wn = buf1;
    const float* lrow = lapS + n * 129;
    for (int k = 1; k < cK; k++) {
        float a0 = 0.f, a1 = 0.f, a2 = 0.f, a3 = 0.f;
        #pragma unroll 8
        for (int j = 0; j < cN; j++) {
            const float l = lrow[j];
            const float4 w = *(const float4*)(Wc + j * 20 + mg * 4);
            a0 = fmaf(l, w.x, a0);
            a1 = fmaf(l, w.y, a1);
            a2 = fmaf(l, w.z, a2);
            a3 = fmaf(l, w.w, a3);
        }
        *(float4*)(Wn + n * 20 + mg * 4) = make_float4(a0, a1, a2, a3);
        ((float4*)(featG + k * (cN * cM)))[t] = make_float4(a0, a1, a2, a3);
        __syncthreads();
        float* tmp = Wc; Wc = Wn; Wn = tmp;
    }
}

// ---------------- K1b: MLP(K->H) + BatchNorm + relu -> g_h1 fp16 ----------------
__global__ void __launch_bounds__(256) k_mlpbn(const float* __restrict__ mlpW,
                                               const float* __restrict__ mlpb,
                                               const float* __restrict__ bng,
                                               const float* __restrict__ bnb) {
    __shared__ float wS[cK * cH];
    __shared__ float bS[cH];
    __shared__ float red[8][32];
    __shared__ float scaleS[cH], shiftS[cH];
    const int b = blockIdx.x, t = threadIdx.x;
    if (t < cK * cH) wS[t] = mlpW[t];
    if (t < cH) bS[t] = mlpb[t];
    __syncthreads();

    const float* fG = g_feat + (size_t)b * (cK * cN * cM);
    float sum[cH], sq[cH];
    #pragma unroll
    for (int c = 0; c < cH; c++) { sum[c] = 0.f; sq[c] = 0.f; }

    for (int r = t; r < cN * cM; r += 256) {
        float f[cK];
        #pragma unroll
        for (int k = 0; k < cK; k++) f[k] = fG[k * (cN * cM) + r];
        #pragma unroll
        for (int c = 0; c < cH; c++) {
            float h = bS[c];
            #pragma unroll
            for (int k = 0; k < cK; k++) h = fmaf(f[k], wS[k * cH + c], h);
            sum[c] += h; sq[c] += h * h;
        }
    }
    #pragma unroll
    for (int c = 0; c < cH; c++)
        for (int o = 16; o; o >>= 1) {
            sum[c] += __shfl_xor_sync(0xffffffffu, sum[c], o);
            sq[c]  += __shfl_xor_sync(0xffffffffu, sq[c],  o);
        }
    const int wid = t >> 5, lane = t & 31;
    if (lane == 0) {
        #pragma unroll
        for (int c = 0; c < cH; c++) { red[wid][c] = sum[c]; red[wid][16 + c] = sq[c]; }
    }
    __syncthreads();
    if (t < 32) {
        float v = 0.f;
        for (int w2 = 0; w2 < 8; w2++) v += red[w2][t];
        red[0][t] = v;
    }
    __syncthreads();
    if (t < cH) {
        const float mu = red[0][t] * (1.f / 2048.f);
        const float var = red[0][16 + t] * (1.f / 2048.f) - mu * mu;
        const float sc = bng[t] * rsqrtf(var + 1e-5f);
        scaleS[t] = sc;
        shiftS[t] = bnb[t] - mu * sc;
    }
    __syncthreads();

    __half* h1G = g_h1 + (size_t)b * (cN * cM * cH);
    for (int r = t; r < cN * cM; r += 256) {
        float f[cK];
        #pragma unroll
        for (int k = 0; k < cK; k++) f[k] = fG[k * (cN * cM) + r];
        float o[cH];
        #pragma unroll
        for (int c = 0; c < cH; c++) {
            float h = bS[c];
            #pragma unroll
            for (int k = 0; k < cK; k++) h = fmaf(f[k], wS[k * cH + c], h);
            o[c] = fmaxf(fmaf(h, scaleS[c], shiftS[c]), 0.f);
        }
        uint4* dst = (uint4*)(h1G + r * cH);
        dst[0] = pack8(o);
        dst[1] = pack8(o + 8);
    }
}

// ---------------- CSR build ----------------
__global__ void k_zero() {
    int i = blockIdx.x * blockDim.x + threadIdx.x;
    if (i < NSUM) g_cnt[i] = 0;
}
__global__ void k_hist(const int* __restrict__ ei) {
    const int stride = gridDim.x * blockDim.x;
    for (int e = blockIdx.x * blockDim.x + threadIdx.x; e < cE; e += stride)
        atomicAdd(&g_cnt[ei[cE + e]], 1);
}
__global__ void __launch_bounds__(512) k_scan() {
    __shared__ int wsum[16], woff[16];
    const int t = threadIdx.x, lane = t & 31, wid = t >> 5;
    const int base = t * 32;
    int s = 0;
    for (int i = 0; i < 32; i++) s += g_cnt[base + i];
    int v = s;
    for (int o = 1; o < 32; o <<= 1) {
        int u = __shfl_up_sync(0xffffffffu, v, o);
        if (lane >= o) v += u;
    }
    if (lane == 31) wsum[wid] = v;
    __syncthreads();
    if (t == 0) {
        int r = 0;
        for (int w2 = 0; w2 < 16; w2++) { woff[w2] = r; r += wsum[w2]; }
    }
    __syncthreads();
    int run = woff[wid] + (v - s);
    for (int i = 0; i < 32; i++) {
        const int c = g_cnt[base + i];
        g_rowptr[base + i] = run;
        g_cursor[base + i] = run;
        run += c;
    }
    if (t == 511) g_rowptr[NSUM] = run;
}
__global__ void k_scatter(const int* __restrict__ ei) {
    const int stride = gridDim.x * blockDim.x;
    for (int e = blockIdx.x * blockDim.x + threadIdx.x; e < cE; e += stride) {
        const int d = ei[cE + e];
        const int p = atomicAdd(&g_cursor[d], 1);
        g_colsrc[p] = ei[e];
    }
}

// ---------------- inline-PTX m16n8k16 HMMA accumulate ----------------
// Accumulates C[16 x NT*8] += A[16 x 16*KT] (row-major, lda halves) @ Bt^T into c[NT][4].
// Bt stored n-major [NT*8][ldb halves] (k contiguous per n == col-major B).
// Fragment map: c[nt][0,1] -> (row g, cols nt*8+2tg,+1); c[nt][2,3] -> (row g+8, same).
template <int KT, int NT>
__device__ __forceinline__ void mma_accum(const __half* __restrict__ A, int lda,
                                          const __half* __restrict__ Bt, int ldb,
                                          int lane, float (*c)[4]) {
    const int g = lane >> 2, tg = lane & 3;
    #pragma unroll
    for (int kt = 0; kt < KT; kt++) {
        const int k0 = kt * 16 + 2 * tg;
        const unsigned a0 = *(const unsigned*)(A + g * lda + k0);
        const unsigned a1 = *(const unsigned*)(A + (g + 8) * lda + k0);
        const unsigned a2 = *(const unsigned*)(A + g * lda + k0 + 8);
        const unsigned a3 = *(const unsigned*)(A + (g + 8) * lda + k0 + 8);
        #pragma unroll
        for (int nt = 0; nt < NT; nt++) {
            const __half* bp = Bt + (nt * 8 + g) * ldb + k0;
            const unsigned b0 = *(const unsigned*)(bp);
            const unsigned b1 = *(const unsigned*)(bp + 8);
            asm volatile(
                "mma.sync.aligned.m16n8k16.row.col.f32.f16.f16.f32 "
                "{%0,%1,%2,%3}, {%4,%5,%6,%7}, {%8,%9}, {%0,%1,%2,%3};\n"
                : "+f"(c[nt][0]), "+f"(c[nt][1]), "+f"(c[nt][2]), "+f"(c[nt][3])
                : "r"(a0), "r"(a1), "r"(a2), "r"(a3), "r"(b0), "r"(b1));
        }
    }
}

// ---------------- K3: fused GIN layer 1 (1 warp/node, warp-synchronous) ----------------
__global__ void __launch_bounds__(256) k_gin1(const float* __restrict__ eps1p,
                                              const float* __restrict__ W1a,
                                              const float* __restrict__ b1a,
                                              const float* __restrict__ W1b,
                                              const float* __restrict__ b1b) {
    extern __shared__ char smraw[];
    float*  ba  = (float*)smraw;               // 64
    float*  bb  = ba + 64;                     // 64
    __half* zt  = (__half*)(bb + 64);          // [128][24]
    __half* at  = zt + 128 * 24;               // [128][72]
    __half* wta = at + 128 * 72;               // [64][24]  n-major, k inner
    __half* wtb = wta + 64 * 24;               // [64][72]
    const int t = threadIdx.x, blk = blockIdx.x;

    for (int i = t; i < 1024; i += 256) {
        const int k = i >> 6, n = i & 63;
        wta[n * 24 + k] = __float2half(W1a[i]);
    }
    for (int i = t; i < 4096; i += 256) {
        const int k = i >> 6, n = i & 63;
        wtb[n * 72 + k] = __float2half(W1b[i]);
    }
    if (t < 64) { ba[t] = b1a[t]; bb[t] = b1b[t]; }
    const float eps1 = 1.f + eps1p[0];
    __syncthreads();   // the ONLY block sync: weights/biases visible to all warps

    const int w = t >> 5, lane = t & 31;
    const int node = blk * 8 + w;
    {
        float a[8];
        #pragma unroll
        for (int j = 0; j < 8; j++) a[j] = 0.f;
        const int s0 = g_rowptr[node], s1 = g_rowptr[node + 1];
        int e = s0;
        for (; e + 4 <= s1; e += 4) {
            const int c0 = g_colsrc[e], c1 = g_colsrc[e + 1];
            const int c2 = g_colsrc[e + 2], c3 = g_colsrc[e + 3];
            const uint4 v0 = ((const uint4*)(g_h1 + c0 * (cM * cH)))[lane];
            const uint4 v1 = ((const uint4*)(g_h1 + c1 * (cM * cH)))[lane];
            const uint4 v2 = ((const uint4*)(g_h1 + c2 * (cM * cH)))[lane];
            const uint4 v3 = ((const uint4*)(g_h1 + c3 * (cM * cH)))[lane];
            acc8(a, v0); acc8(a, v1); acc8(a, v2); acc8(a, v3);
        }
        for (; e < s1; e++) {
            const uint4 v = ((const uint4*)(g_h1 + g_colsrc[e] * (cM * cH)))[lane];
            acc8(a, v);
        }
        const uint4 vs = ((const uint4*)(g_h1 + node * (cM * cH)))[lane];
        fma8(a, vs, eps1);
        // lane covers elements 8*lane..8*lane+7: m = lane>>1, c0 = (lane&1)*8
        *(uint4*)(zt + (w * 16 + (lane >> 1)) * 24 + (lane & 1) * 8) = pack8(a);
    }
    __syncwarp();

    const int g = lane >> 2, tg = lane & 3;
    // GEMM1: z @ W1a  (K=16)
    float c1[8][4];
    #pragma unroll
    for (int nt = 0; nt < 8; nt++)
        #pragma unroll
        for (int j = 0; j < 4; j++) c1[nt][j] = 0.f;
    mma_accum<1, 8>(zt + w * 16 * 24, 24, wta, 24, lane, c1);
    // bias+relu+pack in registers -> at (own warp's rows only)
    #pragma unroll
    for (int nt = 0; nt < 8; nt++) {
        const int col = nt * 8 + 2 * tg;
        const float2 b = *(const float2*)(ba + col);
        *(__half2*)(at + (w * 16 + g) * 72 + col) =
            __floats2half2_rn(fmaxf(c1[nt][0] + b.x, 0.f), fmaxf(c1[nt][1] + b.y, 0.f));
        *(__half2*)(at + (w * 16 + g + 8) * 72 + col) =
            __floats2half2_rn(fmaxf(c1[nt][2] + b.x, 0.f), fmaxf(c1[nt][3] + b.y, 0.f));
    }
    __syncwarp();

    // GEMM2: a @ W1b  (K=64)
    float c2[8][4];
    #pragma unroll
    for (int nt = 0; nt < 8; nt++)
        #pragma unroll
        for (int j = 0; j < 4; j++) c2[nt][j] = 0.f;
    mma_accum<4, 8>(at + w * 16 * 72, 72, wtb, 72, lane, c2);
    // bias+relu+pack -> g_h2 directly from registers
    __half* outG = g_h2 + (size_t)(blk * 128 + w * 16) * cD;
    #pragma unroll
    for (int nt = 0; nt < 8; nt++) {
        const int col = nt * 8 + 2 * tg;
        const float2 b = *(const float2*)(bb + col);
        *(__half2*)(outG + g * cD + col) =
            __floats2half2_rn(fmaxf(c2[nt][0] + b.x, 0.f), fmaxf(c2[nt][1] + b.y, 0.f));
        *(__half2*)(outG + (g + 8) * cD + col) =
            __floats2half2_rn(fmaxf(c2[nt][2] + b.x, 0.f), fmaxf(c2[nt][3] + b.y, 0.f));
    }
}

// ---------------- K4: fused GIN layer 2 — 2 warps per node, pair-synchronous ----------------
// Warp pair (2p, 2p+1) owns one node; warp part q handles d-columns [32q, 32q+32).
// smem z buffer is reused for the GEMM1 activation (WAR fenced by pair barrier).
__global__ void __launch_bounds__(512) k_gin2(const float* __restrict__ eps2p,
                                              const float* __restrict__ W2a,
                                              const float* __restrict__ b2a,
                                              const float* __restrict__ W2b,
                                              const float* __restrict__ b2b,
                                              float* __restrict__ out) {
    extern __shared__ char smraw[];
    float*  ba  = (float*)smraw;               // 64
    float*  bb  = ba + 64;                     // 64
    __half* zt  = (__half*)(bb + 64);          // [128][72]  (z, then reused for a)
    __half* wta = zt + 128 * 72;               // [64][72]
    __half* wtb = wta + 64 * 72;               // [64][72]
    const int t = threadIdx.x, blk = blockIdx.x;

    for (int i = t; i < 4096; i += 512) {
        const int k = i >> 6, n = i & 63;
        wta[n * 72 + k] = __float2half(W2a[i]);
        wtb[n * 72 + k] = __float2half(W2b[i]);
    }
    if (t < 64) { ba[t] = b2a[t]; bb[t] = b2b[t]; }
    const float eps2 = 1.f + eps2p[0];
    __syncthreads();   // the ONLY block sync

    const int w = t >> 5, lane = t & 31;
    const int pair = w >> 1, q = w & 1;        // pair 0..7, part 0..1
    const int node = blk * 8 + pair;
    const int barid = 1 + pair;                // named barriers 1..8, 64 threads each

    // gather: this warp covers 512 halves = d-range [32q, 32q+32) over all 16 m.
    // lane covers 16 halves: m = lane>>1, d0 = q*32 + (lane&1)*16; uint4 u = m*8 + q*4 + (lane&1)*2.
    const int u = (lane >> 1) * 8 + q * 4 + (lane & 1) * 2;
    {
        float a[16];
        #pragma unroll
        for (int j = 0; j < 16; j++) a[j] = 0.f;
        const int s0 = g_rowptr[node], s1 = g_rowptr[node + 1];
        int e = s0;
        for (; e + 4 <= s1; e += 4) {
            const uint4* p0 = (const uint4*)(g_h2 + (size_t)g_colsrc[e] * (cM * cD));
            const uint4* p1 = (const uint4*)(g_h2 + (size_t)g_colsrc[e + 1] * (cM * cD));
            const uint4* p2 = (const uint4*)(g_h2 + (size_t)g_colsrc[e + 2] * (cM * cD));
            const uint4* p3 = (const uint4*)(g_h2 + (size_t)g_colsrc[e + 3] * (cM * cD));
            const uint4 v0a = p0[u], v0b = p0[u + 1];
            const uint4 v1a = p1[u], v1b = p1[u + 1];
            const uint4 v2a = p2[u], v2b = p2[u + 1];
            const uint4 v3a = p3[u], v3b = p3[u + 1];
            acc8(a, v0a); acc8(a + 8, v0b);
            acc8(a, v1a); acc8(a + 8, v1b);
            acc8(a, v2a); acc8(a + 8, v2b);
            acc8(a, v3a); acc8(a + 8, v3b);
        }
        for (; e < s1; e++) {
            const uint4* p0 = (const uint4*)(g_h2 + (size_t)g_colsrc[e] * (cM * cD));
            acc8(a, p0[u]); acc8(a + 8, p0[u + 1]);
        }
        const uint4* ps = (const uint4*)(g_h2 + (size_t)node * (cM * cD));
        fma8(a, ps[u], eps2); fma8(a + 8, ps[u + 1], eps2);
        __half* zp = zt + (pair * 16 + (lane >> 1)) * 72 + q * 32 + (lane & 1) * 16;
        *(uint4*)zp = pack8(a);
        *(uint4*)(zp + 8) = pack8(a + 8);
    }
    asm volatile("bar.sync %0, %1;" :: "r"(barid), "r"(64) : "memory");   // z tile ready

    const int g = lane >> 2, tg = lane & 3;
    const __half* Atile = zt + pair * 16 * 72;

    // GEMM1: z @ W2a  (K=64), this warp computes cols [32q, 32q+32)
    float c1[4][4];
    #pragma unroll
    for (int nt = 0; nt < 4; nt++)
        #pragma unroll
        for (int j = 0; j < 4; j++) c1[nt][j] = 0.f;
    mma_accum<4, 4>(Atile, 72, wta + q * 32 * 72, 72, lane, c1);
    asm volatile("bar.sync %0, %1;" :: "r"(barid), "r"(64) : "memory");   // both warps done reading z

    // bias+relu+pack -> reuse z buffer as activation
    #pragma unroll
    for (int nt = 0; nt < 4; nt++) {
        const int col = q * 32 + nt * 8 + 2 * tg;
        const float2 b = *(const float2*)(ba + col);
        *(__half2*)(zt + (pair * 16 + g) * 72 + col) =
            __floats2half2_rn(fmaxf(c1[nt][0] + b.x, 0.f), fmaxf(c1[nt][1] + b.y, 0.f));
        *(__half2*)(zt + (pair * 16 + g + 8) * 72 + col) =
            __floats2half2_rn(fmaxf(c1[nt][2] + b.x, 0.f), fmaxf(c1[nt][3] + b.y, 0.f));
    }
    asm volatile("bar.sync %0, %1;" :: "r"(barid), "r"(64) : "memory");   // activation ready

    // GEMM2: a @ W2b  (K=64), cols [32q, 32q+32)
    float c2[4][4];
    #pragma unroll
    for (int nt = 0; nt < 4; nt++)
        #pragma unroll
        for (int j = 0; j < 4; j++) c2[nt][j] = 0.f;
    mma_accum<4, 4>(Atile, 72, wtb + q * 32 * 72, 72, lane, c2);

    // bias + relu + m-sum in registers/shuffles (rows g, g+8 local; 8 g-values via shfl)
    #pragma unroll
    for (int nt = 0; nt < 4; nt++) {
        const int col = q * 32 + nt * 8 + 2 * tg;
        const float2 b = *(const float2*)(bb + col);
        float s0 = fmaxf(c2[nt][0] + b.x, 0.f) + fmaxf(c2[nt][2] + b.x, 0.f);
        float s1 = fmaxf(c2[nt][1] + b.y, 0.f) + fmaxf(c2[nt][3] + b.y, 0.f);
        #pragma unroll
        for (int o = 4; o <= 16; o <<= 1) {
            s0 += __shfl_xor_sync(0xffffffffu, s0, o);
            s1 += __shfl_xor_sync(0xffffffffu, s1, o);
        }
        if (g == 0)
            *(float2*)(out + (size_t)node * 64 + col) = make_float2(s0, s1);
    }
}

// ---------------- launch ----------------
extern "C" void kernel_launch(void* const* d_in, const int* in_sizes, int n_in,
                              void* d_out, int out_size) {
    (void)in_sizes; (void)n_in; (void)out_size;
    const float* lap  = (const float*)d_in[0];
    const float* W0   = (const float*)d_in[1];
    const float* mlpW = (const float*)d_in[2];
    const float* mlpb = (const float*)d_in[3];
    const float* bng  = (const float*)d_in[4];
    const float* bnb  = (const float*)d_in[5];
    const float* eps1 = (const float*)d_in[6];
    const float* W1a  = (const float*)d_in[7];
    const float* b1a  = (const float*)d_in[8];
    const float* W1b  = (const float*)d_in[9];
    const float* b1b  = (const float*)d_in[10];
    const float* eps2 = (const float*)d_in[11];
    const float* W2a  = (const float*)d_in[12];
    const float* b2a  = (const float*)d_in[13];
    const float* W2b  = (const float*)d_in[14];
    const float* b2b  = (const float*)d_in[15];
    const int*   ei   = (const int*)d_in[16];
    float* out = (float*)d_out;

    const int sm1 = (128 * 129 + 2 * 128 * 20) * (int)sizeof(float);
    const int sm3 = 128 * 4 + (128 * 24 + 128 * 72 + 64 * 24 + 64 * 72) * 2;   // 37,376 B
    const int sm4 = 128 * 4 + (128 * 72 + 2 * 64 * 72) * 2;                    // 37,376 B
    cudaFuncSetAttribute(k_poly, cudaFuncAttributeMaxDynamicSharedMemorySize, sm1);
    cudaFuncSetAttribute(k_gin1, cudaFuncAttributeMaxDynamicSharedMemorySize, sm3);
    cudaFuncSetAttribute(k_gin2, cudaFuncAttributeMaxDynamicSharedMemorySize, sm4);

    k_poly<<<cB, 512, sm1>>>(lap, W0);
    k_zero<<<(NSUM + 255) / 256, 256>>>();
    k_hist<<<256, 256>>>(ei);
    k_mlpbn<<<cB, 256>>>(mlpW, mlpb, bng, bnb);
    k_scan<<<1, 512>>>();
    k_scatter<<<256, 256>>>(ei);
    k_gin1<<<NSUM / 8, 256, sm3>>>(eps1, W1a, b1a, W1b, b1b);
    k_gin2<<<NSUM / 8, 512, sm4>>>(eps2, W2a, b2a, W2b, b2b, out);
}